// round 2
// baseline (speedup 1.0000x reference)
#include <cuda_runtime.h>
#include <math.h>

#define NB 8
#define C 256
#define C2 128
#define P 4096          // 64*64 pixels
#define COUT3 768

// ---------------- scratch (device globals; no allocs allowed) ----------------
__device__ float g_pos[C * P];                 // positional encoding, 4 MB
__device__ float g_expx[NB * COUT3 * P];       // expansion conv output, 100 MB
__device__ float g_cat[NB * COUT3 * P];        // gated branches (concat), 100 MB
__device__ float g_tmp[NB * C * P];            // W_fus @ x + bc, 33.5 MB
__device__ float g_T[3][NB * P];               // ch_wq logits per branch
__device__ float g_We[3][NB * P];              // w * exp(T) per pixel
__device__ float g_wcov[P];                    // coverage weights for win=6
__device__ float g_xs[3][NB * C];              // sum_p cnt*X
__device__ float g_ys[3][NB * C];              // sum_p cnt*e*X
__device__ float g_Z[3][NB];                   // sum_p cnt*e
__device__ float g_chw[3][NB * C];             // channel gate
__device__ float g_v[3][NB * C];               // spatial-gate projection vector
__device__ float g_beta[3][NB];                // spatial-gate bias
__device__ float g_Wc[C * COUT3];              // W_fus @ W_res
__device__ float g_bc[C];                      // W_fus @ b_res + b_fus

// coverage count for win=6 (kh=14, sh=10, 6 patches)
__device__ __forceinline__ int cov6(int h) {
    int r = 0;
#pragma unroll
    for (int j = 0; j < 6; j++) r += (h >= 10 * j) && (h <= 10 * j + 13);
    return r;
}

__device__ __forceinline__ float sigmoidf_(float x) {
    return 1.0f / (1.0f + expf(-x));
}

// ---------------- K1: positional encoding + coverage weights ----------------
__global__ void pos_kernel() {
    int idx = blockIdx.x * blockDim.x + threadIdx.x;  // < C*P
    int prow = idx >> 8;
    int c = idx & 255;
    int i = prow >> 6;
    int j = prow & 63;
    int k = c & 63;
    float omega = powf(10000.0f, -(float)k / 64.0f);
    float coord = (c < 128) ? (float)i : (float)j;
    float a = coord * omega;
    float val = ((c >> 6) & 1) ? cosf(a) : sinf(a);
    g_pos[idx] = val;
    if (idx < P) {
        int h = idx >> 6, w = idx & 63;
        g_wcov[idx] = (float)(cov6(h) * cov6(w));
    }
}

// ---------------- K2: Wc = W_fus @ W_res (256 x 768) ----------------
__global__ __launch_bounds__(256) void wc_kernel(const float* __restrict__ Wf,
                                                 const float* __restrict__ Wr) {
    int c = blockIdx.x;  // < 768
    __shared__ float col[C];
    col[threadIdx.x] = Wr[threadIdx.x * COUT3 + c];
    __syncthreads();
    int o = threadIdx.x;
    const float* row = Wf + o * C;
    float a = 0.f;
#pragma unroll 8
    for (int m = 0; m < C; m++) a += row[m] * col[m];
    g_Wc[o * COUT3 + c] = a;
}

__global__ __launch_bounds__(256) void bc_kernel(const float* __restrict__ Wf,
                                                 const float* __restrict__ br,
                                                 const float* __restrict__ bf) {
    int o = threadIdx.x;
    float a = 0.f;
#pragma unroll 8
    for (int m = 0; m < C; m++) a += Wf[o * C + m] * br[m];
    g_bc[o] = a + bf[o];
}

// ---------------- f32x2 SGEMM: Y[n,o,p] = sum_c W[o,c]*X[n,c,p] (+bias)(+add) ---
// 128x128x16 tile, 256 threads, 8x8 per-thread micro-tile via fma.rn.f32x2.
__global__ __launch_bounds__(256, 2) void sgemm2_kernel(
    const float* __restrict__ W, const float* __restrict__ X,
    const float* __restrict__ bias, const float* __restrict__ add,
    float* __restrict__ Y, int Cin, int Cout)
{
    __shared__ float2 Ad[16][128];   // W values duplicated into f32x2 pairs
    __shared__ float  Bs[16][128];
    int n = blockIdx.z;
    const float* Xn = X + (size_t)n * Cin * P;
    float* Yn = Y + (size_t)n * Cout * P;
    int row0 = blockIdx.y * 128, col0 = blockIdx.x * 128;
    int tid = threadIdx.x;
    int tx = tid & 15, ty = tid >> 4;

    unsigned long long acc[8][4];
#pragma unroll
    for (int i = 0; i < 8; i++)
#pragma unroll
        for (int j = 0; j < 4; j++) acc[i][j] = 0ull;

    for (int k0 = 0; k0 < Cin; k0 += 16) {
#pragma unroll
        for (int it = 0; it < 2; it++) {
            int idx = it * 256 + tid;          // < 512
            int m = idx >> 2, kq = (idx & 3) * 4;
            float4 v = *(const float4*)&W[(size_t)(row0 + m) * Cin + k0 + kq];
            Ad[kq + 0][m] = make_float2(v.x, v.x);
            Ad[kq + 1][m] = make_float2(v.y, v.y);
            Ad[kq + 2][m] = make_float2(v.z, v.z);
            Ad[kq + 3][m] = make_float2(v.w, v.w);
        }
#pragma unroll
        for (int it = 0; it < 2; it++) {
            int idx = it * 256 + tid;          // < 512
            int k = idx >> 5, p4 = (idx & 31) * 4;
            *(float4*)&Bs[k][p4] = *(const float4*)&Xn[(size_t)(k0 + k) * P + col0 + p4];
        }
        __syncthreads();
#pragma unroll
        for (int k = 0; k < 16; k++) {
            unsigned long long a[8], b[4];
#pragma unroll
            for (int i = 0; i < 8; i++)
                a[i] = *(const unsigned long long*)&Ad[k][ty * 8 + i];
#pragma unroll
            for (int j = 0; j < 4; j++)
                b[j] = *(const unsigned long long*)&Bs[k][tx * 8 + j * 2];
#pragma unroll
            for (int i = 0; i < 8; i++)
#pragma unroll
                for (int j = 0; j < 4; j++)
                    asm("fma.rn.f32x2 %0, %1, %2, %0;"
                        : "+l"(acc[i][j]) : "l"(a[i]), "l"(b[j]));
        }
        __syncthreads();
    }

    const float* an = add ? add + (size_t)n * Cout * P : nullptr;
#pragma unroll
    for (int i = 0; i < 8; i++) {
        int o = row0 + ty * 8 + i;
        float bo = bias ? bias[o] : 0.f;
        size_t base = (size_t)o * P + col0 + tx * 8;
        float r[8];
#pragma unroll
        for (int j = 0; j < 4; j++) {
            float2 v = *(float2*)&acc[i][j];
            r[2 * j] = v.x + bo;
            r[2 * j + 1] = v.y + bo;
        }
        if (an) {
            float4 a0 = *(const float4*)&an[base];
            float4 a1 = *(const float4*)&an[base + 4];
            r[0] += a0.x; r[1] += a0.y; r[2] += a0.z; r[3] += a0.w;
            r[4] += a1.x; r[5] += a1.y; r[6] += a1.z; r[7] += a1.w;
        }
        *(float4*)&Yn[base] = make_float4(r[0], r[1], r[2], r[3]);
        *(float4*)&Yn[base + 4] = make_float4(r[4], r[5], r[6], r[7]);
    }
}

// ---------------- K3: per-pixel ch_wq logits T and w*exp(T) ----------------
__global__ __launch_bounds__(128) void tq_kernel(const float* __restrict__ wq,
                                                 const float* __restrict__ bq) {
    int b = blockIdx.z, n = blockIdx.y;
    int p = blockIdx.x * 128 + threadIdx.x;
    __shared__ float wqs[C];
    for (int c = threadIdx.x; c < C; c += 128) wqs[c] = wq[c];
    __syncthreads();
    const float* E = g_expx + ((size_t)n * COUT3 + b * C) * P;
    float acc = 0.f;
#pragma unroll 8
    for (int c = 0; c < C; c++)
        acc += wqs[c] * (E[(size_t)c * P + p] + g_pos[(size_t)c * P + p]);
    float T = acc + bq[0];
    float w = (b == 2) ? g_wcov[p] : 1.f;
    g_T[b][n * P + p] = T;
    g_We[b][n * P + p] = w * expf(T);
}

// ---------------- K4: per-(branch,n,c) reductions over pixels ----------------
__global__ __launch_bounds__(256) void red_kernel() {
    int b = blockIdx.z, n = blockIdx.y, c = blockIdx.x;
    const float* E = g_expx + ((size_t)n * COUT3 + b * C + c) * P;
    const float* Pp = g_pos + (size_t)c * P;
    const float* Wn = &g_We[b][n * P];
    float xs = 0.f, ys = 0.f, zs = 0.f;
    for (int t = threadIdx.x; t < P; t += 256) {
        float w = (b == 2) ? g_wcov[t] : 1.f;
        float X = E[t] + Pp[t];
        float we = Wn[t];
        xs += w * X;
        ys += we * X;
        zs += we;
    }
    __shared__ float red[256];
    int t = threadIdx.x;
    red[t] = xs; __syncthreads();
    for (int s = 128; s > 0; s >>= 1) { if (t < s) red[t] += red[t + s]; __syncthreads(); }
    if (t == 0) g_xs[b][n * C + c] = red[0];
    __syncthreads();
    red[t] = ys; __syncthreads();
    for (int s = 128; s > 0; s >>= 1) { if (t < s) red[t] += red[t + s]; __syncthreads(); }
    if (t == 0) g_ys[b][n * C + c] = red[0];
    __syncthreads();
    red[t] = zs; __syncthreads();
    for (int s = 128; s > 0; s >>= 1) { if (t < s) red[t] += red[t + s]; __syncthreads(); }
    if (t == 0 && c == 0) g_Z[b][n] = red[0];
}

// ---------------- K5: tiny per-(n,branch) GEMV chains ----------------
__global__ __launch_bounds__(256) void tiny_kernel(
    const float* __restrict__ Wv, const float* __restrict__ bv,
    const float* __restrict__ Wz, const float* __restrict__ bz,
    const float* __restrict__ lg, const float* __restrict__ lb,
    const float* __restrict__ Wqs, const float* __restrict__ bqs,
    const float* __restrict__ Wvs, const float* __restrict__ bvs)
{
    int n = blockIdx.x, b = blockIdx.y;
    __shared__ float y[C], xb[C], zz[C2], sq[C2], wzs[C], red[256];
    int t = threadIdx.x;
    float L = (b == 2) ? 7056.f : 4096.f;
    float Zn = g_Z[b][n];
    y[t] = g_ys[b][n * C + t] / Zn;
    xb[t] = g_xs[b][n * C + t] / L;
    __syncthreads();

    // z = Wv @ y + bv   (128 x 256)
    if (t < C2) {
        float a = 0.f;
        for (int c = 0; c < C; c++) a += Wv[t * C + c] * y[c];
        zz[t] = a + bv[t];
    }
    __syncthreads();

    // wz = Wz @ z + bz  (256 x 128)
    {
        float a = 0.f;
        for (int c2 = 0; c2 < C2; c2++) a += Wz[t * C2 + c2] * zz[c2];
        wzs[t] = a + bz[t];
    }
    __syncthreads();

    // layernorm over 256, sigmoid gate
    red[t] = wzs[t]; __syncthreads();
    for (int s = 128; s > 0; s >>= 1) { if (t < s) red[t] += red[t + s]; __syncthreads(); }
    float m = red[0] / 256.f; __syncthreads();
    float d = wzs[t] - m;
    red[t] = d * d; __syncthreads();
    for (int s = 128; s > 0; s >>= 1) { if (t < s) red[t] += red[t + s]; __syncthreads(); }
    float var = red[0] / 256.f; __syncthreads();
    g_chw[b][n * C + t] = sigmoidf_(d * rsqrtf(var + 1e-5f) * lg[t] + lb[t]);

    // g = Wqs @ xbar + bqs  -> softmax over 128 -> sq
    if (t < C2) {
        float a = 0.f;
        for (int c = 0; c < C; c++) a += Wqs[t * C + c] * xb[c];
        zz[t] = a + bqs[t];
    }
    __syncthreads();
    red[t] = (t < C2) ? zz[t] : -1e30f; __syncthreads();
    for (int s = 128; s > 0; s >>= 1) { if (t < s) red[t] = fmaxf(red[t], red[t + s]); __syncthreads(); }
    float mx = red[0]; __syncthreads();
    float e = (t < C2) ? expf(zz[t] - mx) : 0.f;
    if (t < C2) sq[t] = e;
    red[t] = e; __syncthreads();
    for (int s = 128; s > 0; s >>= 1) { if (t < s) red[t] += red[t + s]; __syncthreads(); }
    float se = red[0]; __syncthreads();
    if (t < C2) sq[t] /= se;
    __syncthreads();

    // v[c] = sum_c2 sq[c2]*Wvs[c2,c];  beta = sq . bvs
    {
        float a = 0.f;
        for (int c2 = 0; c2 < C2; c2++) a += sq[c2] * Wvs[c2 * C + t];
        g_v[b][n * C + t] = a;
    }
    red[t] = (t < C2) ? sq[t] * bvs[t] : 0.f; __syncthreads();
    for (int s = 128; s > 0; s >>= 1) { if (t < s) red[t] += red[t + s]; __syncthreads(); }
    if (t == 0) g_beta[b][n] = red[0];
}

// ---------------- K6: spatial gate S + write f_i + expx into cat ----------------
__global__ __launch_bounds__(128) void sf_kernel() {
    int b = blockIdx.z, n = blockIdx.y;
    int p = blockIdx.x * 128 + threadIdx.x;
    __shared__ float vs[C], cs[C];
    for (int c = threadIdx.x; c < C; c += 128) {
        vs[c] = g_v[b][n * C + c];
        cs[c] = g_chw[b][n * C + c];
    }
    __syncthreads();
    const float* E = g_expx + ((size_t)n * COUT3 + b * C) * P;
    float acc = 0.f;
#pragma unroll 8
    for (int c = 0; c < C; c++)
        acc += vs[c] * (E[(size_t)c * P + p] + g_pos[(size_t)c * P + p]);
    float S = sigmoidf_(acc + g_beta[b][n]);
    float* O = g_cat + ((size_t)n * COUT3 + b * C) * P;
#pragma unroll 4
    for (int c = 0; c < C; c++) {
        float e = E[(size_t)c * P + p];
        float X = e + g_pos[(size_t)c * P + p];
        O[(size_t)c * P + p] = X * (cs[c] + S) + e;
    }
}

// ---------------- host ----------------
extern "C" void kernel_launch(void* const* d_in, const int* in_sizes, int n_in,
                              void* d_out, int out_size) {
    const float* x       = (const float*)d_in[0];
    const float* w_exp   = (const float*)d_in[1];
    const float* b_exp   = (const float*)d_in[2];
    const float* w_res   = (const float*)d_in[3];
    const float* b_res   = (const float*)d_in[4];
    const float* w_fus   = (const float*)d_in[5];
    const float* b_fus   = (const float*)d_in[6];
    const float* ch_wv_w = (const float*)d_in[7];
    const float* ch_wv_b = (const float*)d_in[8];
    const float* ch_wq_w = (const float*)d_in[9];
    const float* ch_wq_b = (const float*)d_in[10];
    const float* ch_wz_w = (const float*)d_in[11];
    const float* ch_wz_b = (const float*)d_in[12];
    const float* ln_g    = (const float*)d_in[13];
    const float* ln_b    = (const float*)d_in[14];
    const float* sp_wv_w = (const float*)d_in[15];
    const float* sp_wv_b = (const float*)d_in[16];
    const float* sp_wq_w = (const float*)d_in[17];
    const float* sp_wq_b = (const float*)d_in[18];

    float *p_expx, *p_cat, *p_tmp, *p_Wc, *p_bc;
    cudaGetSymbolAddress((void**)&p_expx, g_expx);
    cudaGetSymbolAddress((void**)&p_cat, g_cat);
    cudaGetSymbolAddress((void**)&p_tmp, g_tmp);
    cudaGetSymbolAddress((void**)&p_Wc, g_Wc);
    cudaGetSymbolAddress((void**)&p_bc, g_bc);

    pos_kernel<<<(C * P) / 256, 256>>>();
    wc_kernel<<<COUT3, 256>>>(w_fus, w_res);
    bc_kernel<<<1, 256>>>(w_fus, b_res, b_fus);

    // expx = W_exp @ x + b_exp
    sgemm2_kernel<<<dim3(P / 128, COUT3 / 128, NB), 256>>>(
        w_exp, x, b_exp, nullptr, p_expx, C, COUT3);

    // tmp = W_fus @ x + bc   (independent of the branch path)
    sgemm2_kernel<<<dim3(P / 128, C / 128, NB), 256>>>(
        w_fus, x, p_bc, nullptr, p_tmp, C, C);

    tq_kernel<<<dim3(P / 128, NB, 3), 128>>>(ch_wq_w, ch_wq_b);
    red_kernel<<<dim3(C, NB, 3), 256>>>();
    tiny_kernel<<<dim3(NB, 3), 256>>>(ch_wv_w, ch_wv_b, ch_wz_w, ch_wz_b,
                                      ln_g, ln_b, sp_wq_w, sp_wq_b,
                                      sp_wv_w, sp_wv_b);
    sf_kernel<<<dim3(P / 128, NB, 3), 128>>>();

    // out = Wc @ cat + tmp
    sgemm2_kernel<<<dim3(P / 128, C / 128, NB), 256>>>(
        p_Wc, p_cat, nullptr, p_tmp, (float*)d_out, COUT3, C);
}

// round 4
// speedup vs baseline: 1.1921x; 1.1921x over previous
#include <cuda_runtime.h>
#include <cuda_bf16.h>
#include <math.h>
#include <stdint.h>

#define NB 8
#define C 256
#define C2 128
#define P 4096          // 64*64 pixels
#define COUT3 768

// ---------------- scratch (device globals; no allocs allowed) ----------------
__device__ float g_pos[C * P];                 // positional encoding, 4 MB
__device__ float g_expx[NB * COUT3 * P];       // expansion conv output, 100 MB
__device__ float g_cat[NB * COUT3 * P];        // gated branches (concat), 100 MB
__device__ float g_tmp[NB * C * P];            // W_fus @ x + bc, 33.5 MB
__device__ float g_We[3][NB * P];              // w * exp(T) per pixel
__device__ float g_wcov[P];                    // coverage weights for win=6
__device__ float g_xs[3][NB * C];              // sum_p cnt*X
__device__ float g_ys[3][NB * C];              // sum_p cnt*e*X
__device__ float g_Z[3][NB];                   // sum_p cnt*e
__device__ float g_chw[3][NB * C];             // channel gate
__device__ float g_v[3][NB * C];               // spatial-gate projection vector
__device__ float g_beta[3][NB];                // spatial-gate bias
__device__ float g_Wc[C * COUT3];              // W_fus @ W_res
__device__ float g_bc[C];                      // W_fus @ b_res + b_fus

// ================= helpers =================
__device__ __forceinline__ uint32_t smem_u32(const void* p) {
    uint32_t a;
    asm("{ .reg .u64 t; cvta.to.shared.u64 t, %1; cvt.u32.u64 %0, t; }"
        : "=r"(a) : "l"(p));
    return a;
}

__device__ __forceinline__ uint32_t swz(uint32_t b) { return b ^ ((b >> 3) & 0x70); }

__device__ __forceinline__ void split2(float a, float b, uint32_t& hp, uint32_t& lp) {
    __nv_bfloat16 ha = __float2bfloat16_rn(a);
    __nv_bfloat16 hb = __float2bfloat16_rn(b);
    __nv_bfloat16 la = __float2bfloat16_rn(a - __bfloat162float(ha));
    __nv_bfloat16 lb = __float2bfloat16_rn(b - __bfloat162float(hb));
    hp = (uint32_t)__bfloat16_as_ushort(ha) | ((uint32_t)__bfloat16_as_ushort(hb) << 16);
    lp = (uint32_t)__bfloat16_as_ushort(la) | ((uint32_t)__bfloat16_as_ushort(lb) << 16);
}

__device__ __forceinline__ void ldsm4(uint32_t a[4], uint32_t addr) {
    asm volatile("ldmatrix.sync.aligned.m8n8.x4.shared.b16 {%0,%1,%2,%3}, [%4];"
                 : "=r"(a[0]), "=r"(a[1]), "=r"(a[2]), "=r"(a[3]) : "r"(addr));
}
__device__ __forceinline__ void ldsm2(uint32_t b[2], uint32_t addr) {
    asm volatile("ldmatrix.sync.aligned.m8n8.x2.shared.b16 {%0,%1}, [%2];"
                 : "=r"(b[0]), "=r"(b[1]) : "r"(addr));
}
__device__ __forceinline__ void mma16816(float d[4], const uint32_t a[4],
                                         const uint32_t b[2]) {
    asm volatile(
        "mma.sync.aligned.m16n8k16.row.col.f32.bf16.bf16.f32 "
        "{%0,%1,%2,%3}, {%4,%5,%6,%7}, {%8,%9}, {%0,%1,%2,%3};"
        : "+f"(d[0]), "+f"(d[1]), "+f"(d[2]), "+f"(d[3])
        : "r"(a[0]), "r"(a[1]), "r"(a[2]), "r"(a[3]), "r"(b[0]), "r"(b[1]));
}

// ======= mma.sync GEMM: Y[n,o,p] = sum_c W[o,c] X[n,c,p] (+bias[o]) (+add) =======
// Tile M=128 (o), N=128 (p), K-chunk=64 bf16. 3-term hi/lo split, fp32 accum.
// Dynamic smem: Ah, Al, Bh, Bl each 128 rows x 128 bytes (SW128 swizzle) = 64 KB.
#define SM_AH 0
#define SM_AL 16384
#define SM_BH 32768
#define SM_BL 49152
#define SM_TOTAL 65536

__global__ void __launch_bounds__(256)
gemm_mma_kernel(const float* __restrict__ W, const float* __restrict__ X,
                const float* __restrict__ bias, const float* __restrict__ add,
                float* __restrict__ Y, int Cin, int Cout)
{
    extern __shared__ char smem[];
    uint32_t sb = smem_u32(smem);
    int tid = threadIdx.x, wid = tid >> 5, lane = tid & 31;
    int n = blockIdx.z;
    int row0 = blockIdx.y * 128, col0 = blockIdx.x * 128;
    const float* Xn = X + (size_t)n * Cin * P;
    float* Yn = Y + (size_t)n * Cout * P;

    int warp_m = wid >> 2;      // 0..1 -> 64 rows
    int warp_n = wid & 3;       // 0..3 -> 32 cols

    float acc[4][4][4];
#pragma unroll
    for (int i = 0; i < 4; i++)
#pragma unroll
        for (int j = 0; j < 4; j++)
#pragma unroll
            for (int k = 0; k < 4; k++) acc[i][j][k] = 0.f;

    // precomputed lane pieces for ldmatrix addressing
    int l7 = lane & 7;
    int aRowOff = ((lane >> 3) & 1) * 8 + l7;       // + mi*16 + warp_m*64
    int aKOff16 = (lane >> 4) * 16;                 // byte offset within k
    int bKOff16 = ((lane >> 3) & 1) * 16;

    int nchunks = Cin >> 6;
    for (int ch = 0; ch < nchunks; ch++) {
        int c0 = ch << 6;
        if (tid < 128) {
            // A tile: row o = row0 + tid, 64 K-values
            const float* wr = &W[(size_t)(row0 + tid) * Cin + c0];
#pragma unroll 4
            for (int cq = 0; cq < 64; cq += 4) {
                float4 v = *(const float4*)&wr[cq];
                uint32_t h0, l0, h1, l1;
                split2(v.x, v.y, h0, l0);
                split2(v.z, v.w, h1, l1);
                uint32_t off = swz(tid * 128 + cq * 2);  // 8B aligned
                *(uint2*)(smem + SM_AH + off) = make_uint2(h0, h1);
                *(uint2*)(smem + SM_AL + off) = make_uint2(l0, l1);
            }
        } else {
            // B tile: pixel p = col0 + (tid-128), transpose-gather
            int pr = tid - 128;
            const float* xc = &Xn[(size_t)c0 * P + col0 + pr];
#pragma unroll 4
            for (int cc = 0; cc < 64; cc += 4) {
                float x0 = xc[(size_t)(cc + 0) * P];
                float x1 = xc[(size_t)(cc + 1) * P];
                float x2 = xc[(size_t)(cc + 2) * P];
                float x3 = xc[(size_t)(cc + 3) * P];
                uint32_t h0, l0, h1, l1;
                split2(x0, x1, h0, l0);
                split2(x2, x3, h1, l1);
                uint32_t off = swz(pr * 128 + cc * 2);
                *(uint2*)(smem + SM_BH + off) = make_uint2(h0, h1);
                *(uint2*)(smem + SM_BL + off) = make_uint2(l0, l1);
            }
        }
        __syncthreads();

#pragma unroll
        for (int ks = 0; ks < 4; ks++) {
            int kb = ks * 32;  // byte offset of this k16 step (16 bf16 = 32B)
            uint32_t aH[4][4], aL[4][4], bH[4][2], bL[4][2];
#pragma unroll
            for (int mi = 0; mi < 4; mi++) {
                int row = warp_m * 64 + mi * 16 + aRowOff;
                uint32_t off = swz((uint32_t)(row * 128 + kb + aKOff16));
                ldsm4(aH[mi], sb + SM_AH + off);
                ldsm4(aL[mi], sb + SM_AL + off);
            }
#pragma unroll
            for (int ni = 0; ni < 4; ni++) {
                int row = warp_n * 32 + ni * 8 + l7;
                uint32_t off = swz((uint32_t)(row * 128 + kb + bKOff16));
                ldsm2(bH[ni], sb + SM_BH + off);
                ldsm2(bL[ni], sb + SM_BL + off);
            }
#pragma unroll
            for (int mi = 0; mi < 4; mi++)
#pragma unroll
                for (int ni = 0; ni < 4; ni++) {
                    mma16816(acc[mi][ni], aH[mi], bH[ni]);
                    mma16816(acc[mi][ni], aH[mi], bL[ni]);
                    mma16816(acc[mi][ni], aL[mi], bH[ni]);
                }
        }
        __syncthreads();
    }

    // ---- epilogue ----
    int r = lane >> 2, q = lane & 3;
    const float* an = add ? add + (size_t)n * Cout * P : nullptr;
#pragma unroll
    for (int mi = 0; mi < 4; mi++) {
        int o = row0 + warp_m * 64 + mi * 16 + r;
        float b0 = bias ? bias[o] : 0.f;
        float b8 = bias ? bias[o + 8] : 0.f;
#pragma unroll
        for (int ni = 0; ni < 4; ni++) {
            int p = col0 + warp_n * 32 + ni * 8 + q * 2;
            float2 v0 = make_float2(acc[mi][ni][0] + b0, acc[mi][ni][1] + b0);
            float2 v1 = make_float2(acc[mi][ni][2] + b8, acc[mi][ni][3] + b8);
            size_t i0 = (size_t)o * P + p;
            size_t i1 = (size_t)(o + 8) * P + p;
            if (an) {
                float2 a0 = *(const float2*)&an[i0];
                float2 a1 = *(const float2*)&an[i1];
                v0.x += a0.x; v0.y += a0.y;
                v1.x += a1.x; v1.y += a1.y;
            }
            *(float2*)&Yn[i0] = v0;
            *(float2*)&Yn[i1] = v1;
        }
    }
}

// =========================== non-GEMM kernels ===========================
__device__ __forceinline__ int cov6(int h) {
    int r = 0;
#pragma unroll
    for (int j = 0; j < 6; j++) r += (h >= 10 * j) && (h <= 10 * j + 13);
    return r;
}
__device__ __forceinline__ float sigmoidf_(float x) { return 1.0f / (1.0f + expf(-x)); }

__global__ void pos_kernel() {
    int idx = blockIdx.x * blockDim.x + threadIdx.x;  // < C*P
    int prow = idx >> 8;
    int c = idx & 255;
    int i = prow >> 6;
    int j = prow & 63;
    int k = c & 63;
    float omega = powf(10000.0f, -(float)k / 64.0f);
    float coord = (c < 128) ? (float)i : (float)j;
    float a = coord * omega;
    float val = ((c >> 6) & 1) ? cosf(a) : sinf(a);
    g_pos[idx] = val;
    if (idx < P) {
        int h = idx >> 6, w = idx & 63;
        g_wcov[idx] = (float)(cov6(h) * cov6(w));
    }
}

__global__ __launch_bounds__(256) void wc_kernel(const float* __restrict__ Wf,
                                                 const float* __restrict__ Wr) {
    int c = blockIdx.x;  // < 768
    __shared__ float col[C];
    col[threadIdx.x] = Wr[threadIdx.x * COUT3 + c];
    __syncthreads();
    int o = threadIdx.x;
    const float* row = Wf + o * C;
    float a = 0.f;
#pragma unroll 8
    for (int m = 0; m < C; m++) a += row[m] * col[m];
    g_Wc[o * COUT3 + c] = a;
}

__global__ __launch_bounds__(256) void bc_kernel(const float* __restrict__ Wf,
                                                 const float* __restrict__ br,
                                                 const float* __restrict__ bf) {
    int o = threadIdx.x;
    float a = 0.f;
#pragma unroll 8
    for (int m = 0; m < C; m++) a += Wf[o * C + m] * br[m];
    g_bc[o] = a + bf[o];
}

__global__ __launch_bounds__(128) void tq_kernel(const float* __restrict__ wq,
                                                 const float* __restrict__ bq) {
    int b = blockIdx.z, n = blockIdx.y;
    int p = blockIdx.x * 128 + threadIdx.x;
    __shared__ float wqs[C];
    for (int c = threadIdx.x; c < C; c += 128) wqs[c] = wq[c];
    __syncthreads();
    const float* E = g_expx + ((size_t)n * COUT3 + b * C) * P;
    float acc = 0.f;
#pragma unroll 8
    for (int c = 0; c < C; c++)
        acc += wqs[c] * (E[(size_t)c * P + p] + g_pos[(size_t)c * P + p]);
    float T = acc + bq[0];
    float w = (b == 2) ? g_wcov[p] : 1.f;
    g_We[b][n * P + p] = w * expf(T);
}

__global__ __launch_bounds__(256) void red_kernel() {
    int b = blockIdx.z, n = blockIdx.y, c = blockIdx.x;
    const float* E = g_expx + ((size_t)n * COUT3 + b * C + c) * P;
    const float* Pp = g_pos + (size_t)c * P;
    const float* Wn = &g_We[b][n * P];
    float xs = 0.f, ys = 0.f, zs = 0.f;
    for (int t = threadIdx.x; t < P; t += 256) {
        float w = (b == 2) ? g_wcov[t] : 1.f;
        float X = E[t] + Pp[t];
        float we = Wn[t];
        xs += w * X;
        ys += we * X;
        zs += we;
    }
    __shared__ float red[256];
    int t = threadIdx.x;
    red[t] = xs; __syncthreads();
    for (int s = 128; s > 0; s >>= 1) { if (t < s) red[t] += red[t + s]; __syncthreads(); }
    if (t == 0) g_xs[b][n * C + c] = red[0];
    __syncthreads();
    red[t] = ys; __syncthreads();
    for (int s = 128; s > 0; s >>= 1) { if (t < s) red[t] += red[t + s]; __syncthreads(); }
    if (t == 0) g_ys[b][n * C + c] = red[0];
    __syncthreads();
    red[t] = zs; __syncthreads();
    for (int s = 128; s > 0; s >>= 1) { if (t < s) red[t] += red[t + s]; __syncthreads(); }
    if (t == 0 && c == 0) g_Z[b][n] = red[0];
}

__global__ __launch_bounds__(256) void tiny_kernel(
    const float* __restrict__ Wv, const float* __restrict__ bv,
    const float* __restrict__ Wz, const float* __restrict__ bz,
    const float* __restrict__ lg, const float* __restrict__ lb,
    const float* __restrict__ Wqs, const float* __restrict__ bqs,
    const float* __restrict__ Wvs, const float* __restrict__ bvs)
{
    int n = blockIdx.x, b = blockIdx.y;
    __shared__ float y[C], xb[C], zz[C2], sq[C2], wzs[C], red[256];
    int t = threadIdx.x;
    float L = (b == 2) ? 7056.f : 4096.f;
    float Zn = g_Z[b][n];
    y[t] = g_ys[b][n * C + t] / Zn;
    xb[t] = g_xs[b][n * C + t] / L;
    __syncthreads();

    if (t < C2) {
        float a = 0.f;
        for (int c = 0; c < C; c++) a += Wv[t * C + c] * y[c];
        zz[t] = a + bv[t];
    }
    __syncthreads();

    {
        float a = 0.f;
        for (int c2 = 0; c2 < C2; c2++) a += Wz[t * C2 + c2] * zz[c2];
        wzs[t] = a + bz[t];
    }
    __syncthreads();

    red[t] = wzs[t]; __syncthreads();
    for (int s = 128; s > 0; s >>= 1) { if (t < s) red[t] += red[t + s]; __syncthreads(); }
    float m = red[0] / 256.f; __syncthreads();
    float d = wzs[t] - m;
    red[t] = d * d; __syncthreads();
    for (int s = 128; s > 0; s >>= 1) { if (t < s) red[t] += red[t + s]; __syncthreads(); }
    float var = red[0] / 256.f; __syncthreads();
    g_chw[b][n * C + t] = sigmoidf_(d * rsqrtf(var + 1e-5f) * lg[t] + lb[t]);

    if (t < C2) {
        float a = 0.f;
        for (int c = 0; c < C; c++) a += Wqs[t * C + c] * xb[c];
        zz[t] = a + bqs[t];
    }
    __syncthreads();
    red[t] = (t < C2) ? zz[t] : -1e30f; __syncthreads();
    for (int s = 128; s > 0; s >>= 1) { if (t < s) red[t] = fmaxf(red[t], red[t + s]); __syncthreads(); }
    float mx = red[0]; __syncthreads();
    float e = (t < C2) ? expf(zz[t] - mx) : 0.f;
    if (t < C2) sq[t] = e;
    red[t] = e; __syncthreads();
    for (int s = 128; s > 0; s >>= 1) { if (t < s) red[t] += red[t + s]; __syncthreads(); }
    float se = red[0]; __syncthreads();
    if (t < C2) sq[t] /= se;
    __syncthreads();

    {
        float a = 0.f;
        for (int c2 = 0; c2 < C2; c2++) a += sq[c2] * Wvs[c2 * C + t];
        g_v[b][n * C + t] = a;
    }
    red[t] = (t < C2) ? sq[t] * bvs[t] : 0.f; __syncthreads();
    for (int s = 128; s > 0; s >>= 1) { if (t < s) red[t] += red[t + s]; __syncthreads(); }
    if (t == 0) g_beta[b][n] = red[0];
}

__global__ __launch_bounds__(128) void sf_kernel() {
    int b = blockIdx.z, n = blockIdx.y;
    int p = blockIdx.x * 128 + threadIdx.x;
    __shared__ float vs[C], cs[C];
    for (int c = threadIdx.x; c < C; c += 128) {
        vs[c] = g_v[b][n * C + c];
        cs[c] = g_chw[b][n * C + c];
    }
    __syncthreads();
    const float* E = g_expx + ((size_t)n * COUT3 + b * C) * P;
    float acc = 0.f;
#pragma unroll 8
    for (int c = 0; c < C; c++)
        acc += vs[c] * (E[(size_t)c * P + p] + g_pos[(size_t)c * P + p]);
    float S = sigmoidf_(acc + g_beta[b][n]);
    float* O = g_cat + ((size_t)n * COUT3 + b * C) * P;
#pragma unroll 4
    for (int c = 0; c < C; c++) {
        float e = E[(size_t)c * P + p];
        float X = e + g_pos[(size_t)c * P + p];
        O[(size_t)c * P + p] = X * (cs[c] + S) + e;
    }
}

// ---------------- host ----------------
extern "C" void kernel_launch(void* const* d_in, const int* in_sizes, int n_in,
                              void* d_out, int out_size) {
    const float* x       = (const float*)d_in[0];
    const float* w_exp   = (const float*)d_in[1];
    const float* b_exp   = (const float*)d_in[2];
    const float* w_res   = (const float*)d_in[3];
    const float* b_res   = (const float*)d_in[4];
    const float* w_fus   = (const float*)d_in[5];
    const float* b_fus   = (const float*)d_in[6];
    const float* ch_wv_w = (const float*)d_in[7];
    const float* ch_wv_b = (const float*)d_in[8];
    const float* ch_wq_w = (const float*)d_in[9];
    const float* ch_wq_b = (const float*)d_in[10];
    const float* ch_wz_w = (const float*)d_in[11];
    const float* ch_wz_b = (const float*)d_in[12];
    const float* ln_g    = (const float*)d_in[13];
    const float* ln_b    = (const float*)d_in[14];
    const float* sp_wv_w = (const float*)d_in[15];
    const float* sp_wv_b = (const float*)d_in[16];
    const float* sp_wq_w = (const float*)d_in[17];
    const float* sp_wq_b = (const float*)d_in[18];

    float *p_expx, *p_cat, *p_tmp, *p_Wc, *p_bc;
    cudaGetSymbolAddress((void**)&p_expx, g_expx);
    cudaGetSymbolAddress((void**)&p_cat, g_cat);
    cudaGetSymbolAddress((void**)&p_tmp, g_tmp);
    cudaGetSymbolAddress((void**)&p_Wc, g_Wc);
    cudaGetSymbolAddress((void**)&p_bc, g_bc);

    cudaFuncSetAttribute(gemm_mma_kernel,
                         cudaFuncAttributeMaxDynamicSharedMemorySize, SM_TOTAL);

    pos_kernel<<<(C * P) / 256, 256>>>();
    wc_kernel<<<COUT3, 256>>>(w_fus, w_res);
    bc_kernel<<<1, 256>>>(w_fus, b_res, b_fus);

    // expx = W_exp @ x + b_exp
    gemm_mma_kernel<<<dim3(P / 128, COUT3 / 128, NB), 256, SM_TOTAL>>>(
        w_exp, x, b_exp, nullptr, p_expx, C, COUT3);

    // tmp = W_fus @ x + bc
    gemm_mma_kernel<<<dim3(P / 128, C / 128, NB), 256, SM_TOTAL>>>(
        w_fus, x, p_bc, nullptr, p_tmp, C, C);

    tq_kernel<<<dim3(P / 128, NB, 3), 128>>>(ch_wq_w, ch_wq_b);
    red_kernel<<<dim3(C, NB, 3), 256>>>();
    tiny_kernel<<<dim3(NB, 3), 256>>>(ch_wv_w, ch_wv_b, ch_wz_w, ch_wz_b,
                                      ln_g, ln_b, sp_wq_w, sp_wq_b,
                                      sp_wv_w, sp_wv_b);
    sf_kernel<<<dim3(P / 128, NB, 3), 128>>>();

    // out = Wc @ cat + tmp
    gemm_mma_kernel<<<dim3(P / 128, C / 128, NB), 256, SM_TOTAL>>>(
        p_Wc, p_cat, nullptr, p_tmp, (float*)d_out, COUT3, C);
}

// round 5
// speedup vs baseline: 1.5098x; 1.2665x over previous
#include <cuda_runtime.h>
#include <cuda_bf16.h>
#include <math.h>
#include <stdint.h>

#define NB 8
#define C 256
#define C2 128
#define P 4096          // 64*64 pixels
#define COUT3 768
#define KFULL 1024      // 768 gated channels + 256 raw x channels

// ---------------- scratch (device globals; no allocs allowed) ----------------
__device__ float g_pos[C * P];                 // positional encoding, 4 MB
__device__ float g_expx[NB * COUT3 * P];       // expansion conv output, 100 MB
__device__ float g_We[3][NB * P];              // w * exp(T) per pixel
__device__ float g_wcov[P];                    // coverage weights for win=6
__device__ float g_xs[3][NB * C];              // sum_p cnt*X
__device__ float g_ys[3][NB * C];              // sum_p cnt*e*X
__device__ float g_Z[3][NB];                   // sum_p cnt*e
__device__ float g_chw[3][NB * C];             // channel gate
__device__ float g_v[3][NB * C];               // spatial-gate projection vector
__device__ float g_beta[3][NB];                // spatial-gate bias
__device__ float g_S[3][NB * P];               // spatial gate per pixel
__device__ float g_Wcat[C * KFULL];            // [W_fus@W_res | W_fus]
__device__ float g_bc[C];                      // W_fus @ b_res + b_fus

// ================= helpers =================
__device__ __forceinline__ uint32_t smem_u32(const void* p) {
    uint32_t a;
    asm("{ .reg .u64 t; cvta.to.shared.u64 t, %1; cvt.u32.u64 %0, t; }"
        : "=r"(a) : "l"(p));
    return a;
}
__device__ __forceinline__ uint32_t swz(uint32_t b) { return b ^ ((b >> 3) & 0x70); }

__device__ __forceinline__ void split2(float a, float b, uint32_t& hp, uint32_t& lp) {
    __nv_bfloat16 ha = __float2bfloat16_rn(a);
    __nv_bfloat16 hb = __float2bfloat16_rn(b);
    __nv_bfloat16 la = __float2bfloat16_rn(a - __bfloat162float(ha));
    __nv_bfloat16 lb = __float2bfloat16_rn(b - __bfloat162float(hb));
    hp = (uint32_t)__bfloat16_as_ushort(ha) | ((uint32_t)__bfloat16_as_ushort(hb) << 16);
    lp = (uint32_t)__bfloat16_as_ushort(la) | ((uint32_t)__bfloat16_as_ushort(lb) << 16);
}

__device__ __forceinline__ void ldsm4(uint32_t a[4], uint32_t addr) {
    asm volatile("ldmatrix.sync.aligned.m8n8.x4.shared.b16 {%0,%1,%2,%3}, [%4];"
                 : "=r"(a[0]), "=r"(a[1]), "=r"(a[2]), "=r"(a[3]) : "r"(addr));
}
__device__ __forceinline__ void ldsm2(uint32_t b[2], uint32_t addr) {
    asm volatile("ldmatrix.sync.aligned.m8n8.x2.shared.b16 {%0,%1}, [%2];"
                 : "=r"(b[0]), "=r"(b[1]) : "r"(addr));
}
__device__ __forceinline__ void mma16816(float d[4], const uint32_t a[4],
                                         const uint32_t b[2]) {
    asm volatile(
        "mma.sync.aligned.m16n8k16.row.col.f32.bf16.bf16.f32 "
        "{%0,%1,%2,%3}, {%4,%5,%6,%7}, {%8,%9}, {%0,%1,%2,%3};"
        : "+f"(d[0]), "+f"(d[1]), "+f"(d[2]), "+f"(d[3])
        : "r"(a[0]), "r"(a[1]), "r"(a[2]), "r"(a[3]), "r"(b[0]), "r"(b[1]));
}

// ======= mma.sync GEMM: Y[n,o,p] = sum_c A[o,c] B[c,p] (+bias[o]) =======
// Tile M=64, N=64 pixels, K-chunk=64 bf16. hi/lo split, fp32 accum.
// mode 0: B[c,p] = X[n,c,p]   (plain)
// mode 1: B[c,p] = gated-cat for c<768, x[n,c-768,p] for c>=768  (fused epilog-free)
#define SM_AH 0
#define SM_AL 8192
#define SM_BH 16384
#define SM_BL 24576

__global__ void __launch_bounds__(128, 4)
gemm_mma_kernel(const float* __restrict__ W, const float* __restrict__ X,
                const float* __restrict__ bias, float* __restrict__ Y,
                int Cin, int Cout, int mode, const float* __restrict__ xin)
{
    __shared__ char smem[32768];
    uint32_t sb = smem_u32(smem);
    int tid = threadIdx.x, wid = tid >> 5, lane = tid & 31;
    int n = blockIdx.z;
    int row0 = blockIdx.y * 64, col0 = blockIdx.x * 64;
    float* Yn = Y + (size_t)n * Cout * P;

    int warp_m = wid >> 1;      // 0..1 -> 32 rows
    int warp_n = wid & 1;       // 0..1 -> 32 cols

    float acc[2][4][4];
#pragma unroll
    for (int i = 0; i < 2; i++)
#pragma unroll
        for (int j = 0; j < 4; j++)
#pragma unroll
            for (int k = 0; k < 4; k++) acc[i][j][k] = 0.f;

    int l7 = lane & 7;
    int aRowOff = ((lane >> 3) & 1) * 8 + l7;
    int aKOff16 = (lane >> 4) * 16;
    int bKOff16 = ((lane >> 3) & 1) * 16;

    int m_ld = tid & 63, half = tid >> 6;   // loader role

    int nchunks = Cin >> 6;
    for (int ch = 0; ch < nchunks; ch++) {
        int c0 = ch << 6;
        // ---- A tile: 64 rows (o), 64 K-values ----
        {
            const float* wr = &W[(size_t)(row0 + m_ld) * Cin + c0 + half * 32];
#pragma unroll
            for (int cq = 0; cq < 32; cq += 4) {
                float4 v = *(const float4*)&wr[cq];
                uint32_t h0, l0, h1, l1;
                split2(v.x, v.y, h0, l0);
                split2(v.z, v.w, h1, l1);
                uint32_t off = swz((uint32_t)(m_ld * 128 + (half * 32 + cq) * 2));
                *(uint2*)(smem + SM_AH + off) = make_uint2(h0, h1);
                *(uint2*)(smem + SM_AL + off) = make_uint2(l0, l1);
            }
        }
        // ---- B tile: 64 pixel-rows, 64 K-values (transpose-gather) ----
        {
            int p = col0 + m_ld;
            float val[4];
#pragma unroll
            for (int cq = 0; cq < 32; cq += 4) {
                if (mode == 0) {
                    const float* xc = &X[((size_t)n * Cin + c0 + half * 32 + cq) * P + p];
#pragma unroll
                    for (int j = 0; j < 4; j++) val[j] = xc[(size_t)j * P];
                } else if (c0 < COUT3) {
                    int b = c0 >> 8;
                    int cl = (c0 & 255) + half * 32 + cq;
                    float Sp = g_S[b][n * P + p];
                    const float* ec = &X[((size_t)n * COUT3 + c0 + half * 32 + cq) * P + p];
                    const float* pc = &g_pos[(size_t)cl * P + p];
                    const float* cw = &g_chw[b][n * C + cl];
#pragma unroll
                    for (int j = 0; j < 4; j++) {
                        float e = ec[(size_t)j * P];
                        float Xv = e + pc[(size_t)j * P];
                        val[j] = Xv * (cw[j] + Sp) + e;
                    }
                } else {
                    const float* xc = &xin[((size_t)n * C + (c0 - COUT3) + half * 32 + cq) * P + p];
#pragma unroll
                    for (int j = 0; j < 4; j++) val[j] = xc[(size_t)j * P];
                }
                uint32_t h0, l0, h1, l1;
                split2(val[0], val[1], h0, l0);
                split2(val[2], val[3], h1, l1);
                uint32_t off = swz((uint32_t)(m_ld * 128 + (half * 32 + cq) * 2));
                *(uint2*)(smem + SM_BH + off) = make_uint2(h0, h1);
                *(uint2*)(smem + SM_BL + off) = make_uint2(l0, l1);
            }
        }
        __syncthreads();

#pragma unroll
        for (int ks = 0; ks < 4; ks++) {
            int kb = ks * 32;
            uint32_t aH[2][4], aL[2][4], bH[4][2], bL[4][2];
#pragma unroll
            for (int mi = 0; mi < 2; mi++) {
                int row = warp_m * 32 + mi * 16 + aRowOff;
                uint32_t off = swz((uint32_t)(row * 128 + kb + aKOff16));
                ldsm4(aH[mi], sb + SM_AH + off);
                ldsm4(aL[mi], sb + SM_AL + off);
            }
#pragma unroll
            for (int ni = 0; ni < 4; ni++) {
                int row = warp_n * 32 + ni * 8 + l7;
                uint32_t off = swz((uint32_t)(row * 128 + kb + bKOff16));
                ldsm2(bH[ni], sb + SM_BH + off);
                ldsm2(bL[ni], sb + SM_BL + off);
            }
#pragma unroll
            for (int mi = 0; mi < 2; mi++)
#pragma unroll
                for (int ni = 0; ni < 4; ni++) {
                    mma16816(acc[mi][ni], aH[mi], bH[ni]);
                    mma16816(acc[mi][ni], aH[mi], bL[ni]);
                    mma16816(acc[mi][ni], aL[mi], bH[ni]);
                }
        }
        __syncthreads();
    }

    // ---- epilogue ----
    int r = lane >> 2, q = lane & 3;
#pragma unroll
    for (int mi = 0; mi < 2; mi++) {
        int o = row0 + warp_m * 32 + mi * 16 + r;
        float b0 = bias ? bias[o] : 0.f;
        float b8 = bias ? bias[o + 8] : 0.f;
#pragma unroll
        for (int ni = 0; ni < 4; ni++) {
            int p = col0 + warp_n * 32 + ni * 8 + q * 2;
            size_t i0 = (size_t)o * P + p;
            size_t i1 = (size_t)(o + 8) * P + p;
            *(float2*)&Yn[i0] = make_float2(acc[mi][ni][0] + b0, acc[mi][ni][1] + b0);
            *(float2*)&Yn[i1] = make_float2(acc[mi][ni][2] + b8, acc[mi][ni][3] + b8);
        }
    }
}

// =========================== non-GEMM kernels ===========================
__device__ __forceinline__ int cov6(int h) {
    int r = 0;
#pragma unroll
    for (int j = 0; j < 6; j++) r += (h >= 10 * j) && (h <= 10 * j + 13);
    return r;
}
__device__ __forceinline__ float sigmoidf_(float x) { return 1.0f / (1.0f + expf(-x)); }

__global__ void pos_kernel() {
    int idx = blockIdx.x * blockDim.x + threadIdx.x;  // < C*P
    int prow = idx >> 8;
    int c = idx & 255;
    int i = prow >> 6;
    int j = prow & 63;
    int k = c & 63;
    float omega = powf(10000.0f, -(float)k / 64.0f);
    float coord = (c < 128) ? (float)i : (float)j;
    float a = coord * omega;
    float val = ((c >> 6) & 1) ? cosf(a) : sinf(a);
    g_pos[idx] = val;
    if (idx < P) {
        int h = idx >> 6, w = idx & 63;
        g_wcov[idx] = (float)(cov6(h) * cov6(w));
    }
}

// g_Wcat = [W_fus @ W_res | W_fus], bias bc = W_fus @ b_res + b_fus
__global__ __launch_bounds__(256) void wcat_kernel(const float* __restrict__ Wf,
                                                   const float* __restrict__ Wr) {
    int c = blockIdx.x;  // < 1024
    int o = threadIdx.x;
    if (c < COUT3) {
        __shared__ float col[C];
        col[o] = Wr[o * COUT3 + c];
        __syncthreads();
        const float* row = Wf + o * C;
        float a = 0.f;
#pragma unroll 8
        for (int m = 0; m < C; m++) a += row[m] * col[m];
        g_Wcat[o * KFULL + c] = a;
    } else {
        g_Wcat[o * KFULL + c] = Wf[o * C + (c - COUT3)];
    }
}

__global__ __launch_bounds__(256) void bc_kernel(const float* __restrict__ Wf,
                                                 const float* __restrict__ br,
                                                 const float* __restrict__ bf) {
    int o = threadIdx.x;
    float a = 0.f;
#pragma unroll 8
    for (int m = 0; m < C; m++) a += Wf[o * C + m] * br[m];
    g_bc[o] = a + bf[o];
}

__global__ __launch_bounds__(128) void tq_kernel(const float* __restrict__ wq,
                                                 const float* __restrict__ bq) {
    int b = blockIdx.z, n = blockIdx.y;
    int p = blockIdx.x * 128 + threadIdx.x;
    __shared__ float wqs[C];
    for (int c = threadIdx.x; c < C; c += 128) wqs[c] = wq[c];
    __syncthreads();
    const float* E = g_expx + ((size_t)n * COUT3 + b * C) * P;
    float acc = 0.f;
#pragma unroll 8
    for (int c = 0; c < C; c++)
        acc += wqs[c] * (E[(size_t)c * P + p] + g_pos[(size_t)c * P + p]);
    float T = acc + bq[0];
    float w = (b == 2) ? g_wcov[p] : 1.f;
    g_We[b][n * P + p] = w * expf(T);
}

__global__ __launch_bounds__(256) void red_kernel() {
    int b = blockIdx.z, n = blockIdx.y, c = blockIdx.x;
    const float* E = g_expx + ((size_t)n * COUT3 + b * C + c) * P;
    const float* Pp = g_pos + (size_t)c * P;
    const float* Wn = &g_We[b][n * P];
    float xs = 0.f, ys = 0.f, zs = 0.f;
    for (int t = threadIdx.x; t < P; t += 256) {
        float w = (b == 2) ? g_wcov[t] : 1.f;
        float X = E[t] + Pp[t];
        float we = Wn[t];
        xs += w * X;
        ys += we * X;
        zs += we;
    }
    __shared__ float red[256];
    int t = threadIdx.x;
    red[t] = xs; __syncthreads();
    for (int s = 128; s > 0; s >>= 1) { if (t < s) red[t] += red[t + s]; __syncthreads(); }
    if (t == 0) g_xs[b][n * C + c] = red[0];
    __syncthreads();
    red[t] = ys; __syncthreads();
    for (int s = 128; s > 0; s >>= 1) { if (t < s) red[t] += red[t + s]; __syncthreads(); }
    if (t == 0) g_ys[b][n * C + c] = red[0];
    __syncthreads();
    red[t] = zs; __syncthreads();
    for (int s = 128; s > 0; s >>= 1) { if (t < s) red[t] += red[t + s]; __syncthreads(); }
    if (t == 0 && c == 0) g_Z[b][n] = red[0];
}

__global__ __launch_bounds__(256) void tiny_kernel(
    const float* __restrict__ Wv, const float* __restrict__ bv,
    const float* __restrict__ Wz, const float* __restrict__ bz,
    const float* __restrict__ lg, const float* __restrict__ lb,
    const float* __restrict__ Wqs, const float* __restrict__ bqs,
    const float* __restrict__ Wvs, const float* __restrict__ bvs)
{
    int n = blockIdx.x, b = blockIdx.y;
    __shared__ float y[C], xb[C], zz[C2], sq[C2], wzs[C], red[256];
    int t = threadIdx.x;
    float L = (b == 2) ? 7056.f : 4096.f;
    float Zn = g_Z[b][n];
    y[t] = g_ys[b][n * C + t] / Zn;
    xb[t] = g_xs[b][n * C + t] / L;
    __syncthreads();

    if (t < C2) {
        float a = 0.f;
        for (int c = 0; c < C; c++) a += Wv[t * C + c] * y[c];
        zz[t] = a + bv[t];
    }
    __syncthreads();

    {
        float a = 0.f;
        for (int c2 = 0; c2 < C2; c2++) a += Wz[t * C2 + c2] * zz[c2];
        wzs[t] = a + bz[t];
    }
    __syncthreads();

    red[t] = wzs[t]; __syncthreads();
    for (int s = 128; s > 0; s >>= 1) { if (t < s) red[t] += red[t + s]; __syncthreads(); }
    float m = red[0] / 256.f; __syncthreads();
    float d = wzs[t] - m;
    red[t] = d * d; __syncthreads();
    for (int s = 128; s > 0; s >>= 1) { if (t < s) red[t] += red[t + s]; __syncthreads(); }
    float var = red[0] / 256.f; __syncthreads();
    g_chw[b][n * C + t] = sigmoidf_(d * rsqrtf(var + 1e-5f) * lg[t] + lb[t]);

    if (t < C2) {
        float a = 0.f;
        for (int c = 0; c < C; c++) a += Wqs[t * C + c] * xb[c];
        zz[t] = a + bqs[t];
    }
    __syncthreads();
    red[t] = (t < C2) ? zz[t] : -1e30f; __syncthreads();
    for (int s = 128; s > 0; s >>= 1) { if (t < s) red[t] = fmaxf(red[t], red[t + s]); __syncthreads(); }
    float mx = red[0]; __syncthreads();
    float e = (t < C2) ? expf(zz[t] - mx) : 0.f;
    if (t < C2) sq[t] = e;
    red[t] = e; __syncthreads();
    for (int s = 128; s > 0; s >>= 1) { if (t < s) red[t] += red[t + s]; __syncthreads(); }
    float se = red[0]; __syncthreads();
    if (t < C2) sq[t] /= se;
    __syncthreads();

    {
        float a = 0.f;
        for (int c2 = 0; c2 < C2; c2++) a += sq[c2] * Wvs[c2 * C + t];
        g_v[b][n * C + t] = a;
    }
    red[t] = (t < C2) ? sq[t] * bvs[t] : 0.f; __syncthreads();
    for (int s = 128; s > 0; s >>= 1) { if (t < s) red[t] += red[t + s]; __syncthreads(); }
    if (t == 0) g_beta[b][n] = red[0];
}

// S-only kernel: spatial gate per pixel (gating itself is fused into final GEMM)
__global__ __launch_bounds__(128) void s_kernel() {
    int b = blockIdx.z, n = blockIdx.y;
    int p = blockIdx.x * 128 + threadIdx.x;
    __shared__ float vs[C];
    for (int c = threadIdx.x; c < C; c += 128) vs[c] = g_v[b][n * C + c];
    __syncthreads();
    const float* E = g_expx + ((size_t)n * COUT3 + b * C) * P;
    float acc = 0.f;
#pragma unroll 8
    for (int c = 0; c < C; c++)
        acc += vs[c] * (E[(size_t)c * P + p] + g_pos[(size_t)c * P + p]);
    g_S[b][n * P + p] = sigmoidf_(acc + g_beta[b][n]);
}

// ---------------- host ----------------
extern "C" void kernel_launch(void* const* d_in, const int* in_sizes, int n_in,
                              void* d_out, int out_size) {
    const float* x       = (const float*)d_in[0];
    const float* w_exp   = (const float*)d_in[1];
    const float* b_exp   = (const float*)d_in[2];
    const float* w_res   = (const float*)d_in[3];
    const float* b_res   = (const float*)d_in[4];
    const float* w_fus   = (const float*)d_in[5];
    const float* b_fus   = (const float*)d_in[6];
    const float* ch_wv_w = (const float*)d_in[7];
    const float* ch_wv_b = (const float*)d_in[8];
    const float* ch_wq_w = (const float*)d_in[9];
    const float* ch_wq_b = (const float*)d_in[10];
    const float* ch_wz_w = (const float*)d_in[11];
    const float* ch_wz_b = (const float*)d_in[12];
    const float* ln_g    = (const float*)d_in[13];
    const float* ln_b    = (const float*)d_in[14];
    const float* sp_wv_w = (const float*)d_in[15];
    const float* sp_wv_b = (const float*)d_in[16];
    const float* sp_wq_w = (const float*)d_in[17];
    const float* sp_wq_b = (const float*)d_in[18];

    float *p_expx, *p_Wcat, *p_bc;
    cudaGetSymbolAddress((void**)&p_expx, g_expx);
    cudaGetSymbolAddress((void**)&p_Wcat, g_Wcat);
    cudaGetSymbolAddress((void**)&p_bc, g_bc);

    pos_kernel<<<(C * P) / 256, 256>>>();
    wcat_kernel<<<KFULL, 256>>>(w_fus, w_res);
    bc_kernel<<<1, 256>>>(w_fus, b_res, b_fus);

    // expx = W_exp @ x + b_exp
    gemm_mma_kernel<<<dim3(P / 64, COUT3 / 64, NB), 128>>>(
        w_exp, x, b_exp, p_expx, C, COUT3, 0, nullptr);

    tq_kernel<<<dim3(P / 128, NB, 3), 128>>>(ch_wq_w, ch_wq_b);
    red_kernel<<<dim3(C, NB, 3), 256>>>();
    tiny_kernel<<<dim3(NB, 3), 256>>>(ch_wv_w, ch_wv_b, ch_wz_w, ch_wz_b,
                                      ln_g, ln_b, sp_wq_w, sp_wq_b,
                                      sp_wv_w, sp_wv_b);
    s_kernel<<<dim3(P / 128, NB, 3), 128>>>();

    // out = [Wc | W_fus] @ [gated-cat ; x] + bc   (gating fused into B-loader)
    gemm_mma_kernel<<<dim3(P / 64, C / 64, NB), 128>>>(
        p_Wcat, p_expx, p_bc, (float*)d_out, KFULL, C, 1, x);
}

// round 6
// speedup vs baseline: 1.8662x; 1.2361x over previous
#include <cuda_runtime.h>
#include <cuda_bf16.h>
#include <math.h>
#include <stdint.h>

#define NB 8
#define C 256
#define C2 128
#define P 4096          // 64*64 pixels
#define COUT3 768
#define KFULL 1024      // 768 gated channels + 256 raw x channels

// ---------------- scratch (device globals; no allocs allowed) ----------------
__device__ float g_pos[C * P];                 // positional encoding, 4 MB
__device__ float g_expx[NB * COUT3 * P];       // expansion conv output, 100 MB
__device__ float g_We[3][NB * P];              // w * exp(T) per pixel
__device__ float g_wcov[P];                    // coverage weights for win=6
__device__ float g_xs[3][NB * C];              // sum_p cnt*X
__device__ float g_ys[3][NB * C];              // sum_p cnt*e*X
__device__ float g_Z[3][NB];                   // sum_p cnt*e
__device__ float g_chw[3][NB * C];             // channel gate
__device__ float g_v[3][NB * C];               // spatial-gate projection vector
__device__ float g_beta[3][NB];                // spatial-gate bias
__device__ float g_S[3][NB * P];               // spatial gate per pixel
__device__ float g_bc[C];                      // W_fus @ b_res + b_fus

// pre-split operands (bf16 hi/lo)
__device__ __nv_bfloat16 g_WexpH[COUT3 * C], g_WexpL[COUT3 * C];
__device__ __nv_bfloat16 g_WcatH[C * KFULL], g_WcatL[C * KFULL];
__device__ __nv_bfloat16 g_xh[NB * P * C], g_xl[NB * P * C];   // [n][p][c]

// ================= helpers =================
__device__ __forceinline__ uint32_t smem_u32(const void* p) {
    uint32_t a;
    asm("{ .reg .u64 t; cvta.to.shared.u64 t, %1; cvt.u32.u64 %0, t; }"
        : "=r"(a) : "l"(p));
    return a;
}
__device__ __forceinline__ uint32_t swz(uint32_t b) { return b ^ ((b >> 3) & 0x70); }

__device__ __forceinline__ void split2(float a, float b, uint32_t& hp, uint32_t& lp) {
    __nv_bfloat16 ha = __float2bfloat16_rn(a);
    __nv_bfloat16 hb = __float2bfloat16_rn(b);
    __nv_bfloat16 la = __float2bfloat16_rn(a - __bfloat162float(ha));
    __nv_bfloat16 lb = __float2bfloat16_rn(b - __bfloat162float(hb));
    hp = (uint32_t)__bfloat16_as_ushort(ha) | ((uint32_t)__bfloat16_as_ushort(hb) << 16);
    lp = (uint32_t)__bfloat16_as_ushort(la) | ((uint32_t)__bfloat16_as_ushort(lb) << 16);
}

__device__ __forceinline__ void ldsm4(uint32_t a[4], uint32_t addr) {
    asm volatile("ldmatrix.sync.aligned.m8n8.x4.shared.b16 {%0,%1,%2,%3}, [%4];"
                 : "=r"(a[0]), "=r"(a[1]), "=r"(a[2]), "=r"(a[3]) : "r"(addr));
}
__device__ __forceinline__ void mma16816(float d[4], const uint32_t a[4],
                                         const uint32_t b0, const uint32_t b1) {
    asm volatile(
        "mma.sync.aligned.m16n8k16.row.col.f32.bf16.bf16.f32 "
        "{%0,%1,%2,%3}, {%4,%5,%6,%7}, {%8,%9}, {%0,%1,%2,%3};"
        : "+f"(d[0]), "+f"(d[1]), "+f"(d[2]), "+f"(d[3])
        : "r"(a[0]), "r"(a[1]), "r"(a[2]), "r"(a[3]), "r"(b0), "r"(b1));
}
__device__ __forceinline__ void cpasync16(uint32_t dst, const void* src) {
    asm volatile("cp.async.ca.shared.global [%0], [%1], 16;" :: "r"(dst), "l"(src));
}
__device__ __forceinline__ void cpasync_wait() {
    asm volatile("cp.async.commit_group;\n\tcp.async.wait_group 0;" ::: "memory");
}

// ======= mma.sync GEMM v3: Y[n,o,p] = sum_c A[o,c] B[c,p] + bias[o] =======
// CTA 256 thr, tile M=128 x N=128, K-chunk 64, warp tile 64x32 (mi=4, ni=4).
// A from pre-split WH/WL via cp.async. B (mode 0 / x-tail) from pre-split
// transposed xT via cp.async; B gated part computed in-loader.
#define SMA_H 0
#define SMA_L 16384
#define SMB_H 32768
#define SMB_L 49152
#define SM_BYTES 65536

__global__ void __launch_bounds__(256, 2)
gemm_mma3(const __nv_bfloat16* __restrict__ WH, const __nv_bfloat16* __restrict__ WL,
          const float* __restrict__ bias, float* __restrict__ Y,
          int Cin, int Cout, int mode)
{
    extern __shared__ char smem[];
    uint32_t sb = smem_u32(smem);
    int tid = threadIdx.x, wid = tid >> 5, lane = tid & 31;
    int n = blockIdx.z;
    int row0 = blockIdx.y * 128, col0 = blockIdx.x * 128;
    float* Yn = Y + (size_t)n * Cout * P;

    int warp_m = wid >> 2;   // 0..1 -> 64 rows
    int warp_n = wid & 3;    // 0..3 -> 32 cols

    float acc[4][4][4];
#pragma unroll
    for (int i = 0; i < 4; i++)
#pragma unroll
        for (int j = 0; j < 4; j++)
#pragma unroll
            for (int k = 0; k < 4; k++) acc[i][j][k] = 0.f;

    int l7 = lane & 7;
    int aRowOff = ((lane >> 3) & 1) * 8 + l7;
    int aKOff16 = (lane >> 4) * 16;
    int bRowOff = ((lane >> 4) & 1) * 8 + l7;
    int bColOff = ((lane >> 3) & 1) * 16;

    int nchunks = Cin >> 6;
    for (int ch = 0; ch < nchunks; ch++) {
        int c0 = ch << 6;
        // ---- A tile: 128 rows x 64 k, hi+lo, pure cp.async ----
#pragma unroll
        for (int i = 0; i < 8; i++) {
            int idx = i * 256 + tid;
            int row = idx >> 4, slot = idx & 15;
            int til = slot >> 3, chunk = slot & 7;
            const __nv_bfloat16* src =
                (til ? WL : WH) + (size_t)(row0 + row) * Cin + c0 + chunk * 8;
            uint32_t dst = sb + (til ? SMA_L : SMA_H) + swz((uint32_t)(row * 128 + chunk * 16));
            cpasync16(dst, src);
        }
        // ---- B tile: 128 pixel-rows x 64 k ----
        bool gated = (mode == 1) && (c0 < COUT3);
        if (!gated) {
            int xc0 = (mode == 1) ? c0 - COUT3 : c0;
#pragma unroll
            for (int i = 0; i < 8; i++) {
                int idx = i * 256 + tid;
                int row = idx >> 4, slot = idx & 15;
                int til = slot >> 3, chunk = slot & 7;
                const __nv_bfloat16* src =
                    (til ? g_xl : g_xh) + ((size_t)n * P + col0 + row) * C + xc0 + chunk * 8;
                uint32_t dst = sb + (til ? SMB_L : SMB_H) + swz((uint32_t)(row * 128 + chunk * 16));
                cpasync16(dst, src);
            }
        } else {
            int row = tid & 127, half = tid >> 7;
            int pg = col0 + row;
            int b = c0 >> 8;
            float Sp = g_S[b][n * P + pg];
#pragma unroll
            for (int cq = 0; cq < 32; cq += 4) {
                int c_loc = half * 32 + cq;
                int cglob = c0 + c_loc;
                int cl = (c0 & 255) + c_loc;
                const float* ec = &g_expx[((size_t)n * COUT3 + cglob) * P + pg];
                const float* pc = &g_pos[(size_t)cl * P + pg];
                const float* cw = &g_chw[b][n * C + cl];
                float val[4];
#pragma unroll
                for (int j = 0; j < 4; j++) {
                    float e = ec[(size_t)j * P];
                    float Xv = e + pc[(size_t)j * P];
                    val[j] = Xv * (cw[j] + Sp) + e;
                }
                uint32_t h0, l0, h1, l1;
                split2(val[0], val[1], h0, l0);
                split2(val[2], val[3], h1, l1);
                uint32_t off = swz((uint32_t)(row * 128 + c_loc * 2));
                *(uint2*)(smem + SMB_H + off) = make_uint2(h0, h1);
                *(uint2*)(smem + SMB_L + off) = make_uint2(l0, l1);
            }
        }
        cpasync_wait();
        __syncthreads();

#pragma unroll
        for (int ks = 0; ks < 4; ks++) {
            int kb = ks * 32;
            uint32_t aH[4][4], aL[4][4];
#pragma unroll
            for (int mi = 0; mi < 4; mi++) {
                int row = warp_m * 64 + mi * 16 + aRowOff;
                uint32_t off = swz((uint32_t)(row * 128 + kb + aKOff16));
                ldsm4(aH[mi], sb + SMA_H + off);
                ldsm4(aL[mi], sb + SMA_L + off);
            }
#pragma unroll
            for (int nip = 0; nip < 2; nip++) {
                int row = warp_n * 32 + nip * 16 + bRowOff;
                uint32_t off = swz((uint32_t)(row * 128 + kb + bColOff));
                uint32_t bH[4], bL[4];
                ldsm4(bH, sb + SMB_H + off);
                ldsm4(bL, sb + SMB_L + off);
#pragma unroll
                for (int mi = 0; mi < 4; mi++) {
                    mma16816(acc[mi][2 * nip], aH[mi], bH[0], bH[1]);
                    mma16816(acc[mi][2 * nip], aH[mi], bL[0], bL[1]);
                    mma16816(acc[mi][2 * nip], aL[mi], bH[0], bH[1]);
                    mma16816(acc[mi][2 * nip + 1], aH[mi], bH[2], bH[3]);
                    mma16816(acc[mi][2 * nip + 1], aH[mi], bL[2], bL[3]);
                    mma16816(acc[mi][2 * nip + 1], aL[mi], bH[2], bH[3]);
                }
            }
        }
        __syncthreads();
    }

    // ---- epilogue ----
    int r = lane >> 2, q = lane & 3;
#pragma unroll
    for (int mi = 0; mi < 4; mi++) {
        int o = row0 + warp_m * 64 + mi * 16 + r;
        float b0 = bias[o];
        float b8 = bias[o + 8];
#pragma unroll
        for (int ni = 0; ni < 4; ni++) {
            int p = col0 + warp_n * 32 + ni * 8 + q * 2;
            size_t i0 = (size_t)o * P + p;
            size_t i1 = (size_t)(o + 8) * P + p;
            *(float2*)&Yn[i0] = make_float2(acc[mi][ni][0] + b0, acc[mi][ni][1] + b0);
            *(float2*)&Yn[i1] = make_float2(acc[mi][ni][2] + b8, acc[mi][ni][3] + b8);
        }
    }
}

// =========================== prep kernels ===========================
__global__ void wsplit_kernel(const float* __restrict__ W,
                              __nv_bfloat16* __restrict__ H,
                              __nv_bfloat16* __restrict__ L, int total) {
    int idx = blockIdx.x * 256 + threadIdx.x;
    if (idx < total) {
        float v = W[idx];
        __nv_bfloat16 h = __float2bfloat16_rn(v);
        H[idx] = h;
        L[idx] = __float2bfloat16_rn(v - __bfloat162float(h));
    }
}

// transpose + split x: [n][c][p] -> xh/xl [n][p][c]
__global__ __launch_bounds__(256) void xprep_kernel(const float* __restrict__ x) {
    __shared__ float tile[32][33];
    int n = blockIdx.z;
    int p0 = blockIdx.x * 32, c0 = blockIdx.y * 32;
    int tx = threadIdx.x & 31, ty = threadIdx.x >> 5;  // 32x8
    for (int i = ty; i < 32; i += 8)
        tile[i][tx] = x[((size_t)n * C + c0 + i) * P + p0 + tx];
    __syncthreads();
    for (int i = ty; i < 32; i += 8) {
        float v = tile[tx][i];   // (c = c0+tx, p = p0+i)
        __nv_bfloat16 h = __float2bfloat16_rn(v);
        size_t dst = ((size_t)n * P + p0 + i) * C + c0 + tx;
        g_xh[dst] = h;
        g_xl[dst] = __float2bfloat16_rn(v - __bfloat162float(h));
    }
}

// g_WcatH/L = split([W_fus @ W_res | W_fus]);  bc computed separately
__global__ __launch_bounds__(256) void wcat_kernel(const float* __restrict__ Wf,
                                                   const float* __restrict__ Wr) {
    int c = blockIdx.x;  // < 1024
    int o = threadIdx.x;
    float a;
    if (c < COUT3) {
        __shared__ float col[C];
        col[o] = Wr[o * COUT3 + c];
        __syncthreads();
        const float* row = Wf + o * C;
        a = 0.f;
#pragma unroll 8
        for (int m = 0; m < C; m++) a += row[m] * col[m];
    } else {
        a = Wf[o * C + (c - COUT3)];
    }
    __nv_bfloat16 h = __float2bfloat16_rn(a);
    g_WcatH[o * KFULL + c] = h;
    g_WcatL[o * KFULL + c] = __float2bfloat16_rn(a - __bfloat162float(h));
}

__global__ __launch_bounds__(256) void bc_kernel(const float* __restrict__ Wf,
                                                 const float* __restrict__ br,
                                                 const float* __restrict__ bf) {
    int o = threadIdx.x;
    float a = 0.f;
#pragma unroll 8
    for (int m = 0; m < C; m++) a += Wf[o * C + m] * br[m];
    g_bc[o] = a + bf[o];
}

// =========================== non-GEMM kernels ===========================
__device__ __forceinline__ int cov6(int h) {
    int r = 0;
#pragma unroll
    for (int j = 0; j < 6; j++) r += (h >= 10 * j) && (h <= 10 * j + 13);
    return r;
}
__device__ __forceinline__ float sigmoidf_(float x) { return 1.0f / (1.0f + expf(-x)); }

__global__ void pos_kernel() {
    int idx = blockIdx.x * blockDim.x + threadIdx.x;  // < C*P
    int prow = idx >> 8;
    int c = idx & 255;
    int i = prow >> 6;
    int j = prow & 63;
    int k = c & 63;
    float omega = powf(10000.0f, -(float)k / 64.0f);
    float coord = (c < 128) ? (float)i : (float)j;
    float a = coord * omega;
    float val = ((c >> 6) & 1) ? cosf(a) : sinf(a);
    g_pos[idx] = val;
    if (idx < P) {
        int h = idx >> 6, w = idx & 63;
        g_wcov[idx] = (float)(cov6(h) * cov6(w));
    }
}

__global__ __launch_bounds__(128) void tq_kernel(const float* __restrict__ wq,
                                                 const float* __restrict__ bq) {
    int b = blockIdx.z, n = blockIdx.y;
    int p = blockIdx.x * 128 + threadIdx.x;
    __shared__ float wqs[C];
    for (int c = threadIdx.x; c < C; c += 128) wqs[c] = wq[c];
    __syncthreads();
    const float* E = g_expx + ((size_t)n * COUT3 + b * C) * P;
    float acc = 0.f;
#pragma unroll 8
    for (int c = 0; c < C; c++)
        acc += wqs[c] * (E[(size_t)c * P + p] + g_pos[(size_t)c * P + p]);
    float T = acc + bq[0];
    float w = (b == 2) ? g_wcov[p] : 1.f;
    g_We[b][n * P + p] = w * expf(T);
}

__global__ __launch_bounds__(256) void red_kernel() {
    int b = blockIdx.z, n = blockIdx.y, c = blockIdx.x;
    const float* E = g_expx + ((size_t)n * COUT3 + b * C + c) * P;
    const float* Pp = g_pos + (size_t)c * P;
    const float* Wn = &g_We[b][n * P];
    float xs = 0.f, ys = 0.f, zs = 0.f;
    for (int t = threadIdx.x; t < P; t += 256) {
        float w = (b == 2) ? g_wcov[t] : 1.f;
        float X = E[t] + Pp[t];
        float we = Wn[t];
        xs += w * X;
        ys += we * X;
        zs += we;
    }
    __shared__ float red[256];
    int t = threadIdx.x;
    red[t] = xs; __syncthreads();
    for (int s = 128; s > 0; s >>= 1) { if (t < s) red[t] += red[t + s]; __syncthreads(); }
    if (t == 0) g_xs[b][n * C + c] = red[0];
    __syncthreads();
    red[t] = ys; __syncthreads();
    for (int s = 128; s > 0; s >>= 1) { if (t < s) red[t] += red[t + s]; __syncthreads(); }
    if (t == 0) g_ys[b][n * C + c] = red[0];
    __syncthreads();
    red[t] = zs; __syncthreads();
    for (int s = 128; s > 0; s >>= 1) { if (t < s) red[t] += red[t + s]; __syncthreads(); }
    if (t == 0 && c == 0) g_Z[b][n] = red[0];
}

__global__ __launch_bounds__(256) void tiny_kernel(
    const float* __restrict__ Wv, const float* __restrict__ bv,
    const float* __restrict__ Wz, const float* __restrict__ bz,
    const float* __restrict__ lg, const float* __restrict__ lb,
    const float* __restrict__ Wqs, const float* __restrict__ bqs,
    const float* __restrict__ Wvs, const float* __restrict__ bvs)
{
    int n = blockIdx.x, b = blockIdx.y;
    __shared__ float y[C], xb[C], zz[C2], sq[C2], wzs[C], red[256];
    int t = threadIdx.x;
    float L = (b == 2) ? 7056.f : 4096.f;
    float Zn = g_Z[b][n];
    y[t] = g_ys[b][n * C + t] / Zn;
    xb[t] = g_xs[b][n * C + t] / L;
    __syncthreads();

    if (t < C2) {
        float a = 0.f;
        for (int c = 0; c < C; c++) a += Wv[t * C + c] * y[c];
        zz[t] = a + bv[t];
    }
    __syncthreads();

    {
        float a = 0.f;
        for (int c2 = 0; c2 < C2; c2++) a += Wz[t * C2 + c2] * zz[c2];
        wzs[t] = a + bz[t];
    }
    __syncthreads();

    red[t] = wzs[t]; __syncthreads();
    for (int s = 128; s > 0; s >>= 1) { if (t < s) red[t] += red[t + s]; __syncthreads(); }
    float m = red[0] / 256.f; __syncthreads();
    float d = wzs[t] - m;
    red[t] = d * d; __syncthreads();
    for (int s = 128; s > 0; s >>= 1) { if (t < s) red[t] += red[t + s]; __syncthreads(); }
    float var = red[0] / 256.f; __syncthreads();
    g_chw[b][n * C + t] = sigmoidf_(d * rsqrtf(var + 1e-5f) * lg[t] + lb[t]);

    if (t < C2) {
        float a = 0.f;
        for (int c = 0; c < C; c++) a += Wqs[t * C + c] * xb[c];
        zz[t] = a + bqs[t];
    }
    __syncthreads();
    red[t] = (t < C2) ? zz[t] : -1e30f; __syncthreads();
    for (int s = 128; s > 0; s >>= 1) { if (t < s) red[t] = fmaxf(red[t], red[t + s]); __syncthreads(); }
    float mx = red[0]; __syncthreads();
    float e = (t < C2) ? expf(zz[t] - mx) : 0.f;
    if (t < C2) sq[t] = e;
    red[t] = e; __syncthreads();
    for (int s = 128; s > 0; s >>= 1) { if (t < s) red[t] += red[t + s]; __syncthreads(); }
    float se = red[0]; __syncthreads();
    if (t < C2) sq[t] /= se;
    __syncthreads();

    {
        float a = 0.f;
        for (int c2 = 0; c2 < C2; c2++) a += sq[c2] * Wvs[c2 * C + t];
        g_v[b][n * C + t] = a;
    }
    red[t] = (t < C2) ? sq[t] * bvs[t] : 0.f; __syncthreads();
    for (int s = 128; s > 0; s >>= 1) { if (t < s) red[t] += red[t + s]; __syncthreads(); }
    if (t == 0) g_beta[b][n] = red[0];
}

__global__ __launch_bounds__(128) void s_kernel() {
    int b = blockIdx.z, n = blockIdx.y;
    int p = blockIdx.x * 128 + threadIdx.x;
    __shared__ float vs[C];
    for (int c = threadIdx.x; c < C; c += 128) vs[c] = g_v[b][n * C + c];
    __syncthreads();
    const float* E = g_expx + ((size_t)n * COUT3 + b * C) * P;
    float acc = 0.f;
#pragma unroll 8
    for (int c = 0; c < C; c++)
        acc += vs[c] * (E[(size_t)c * P + p] + g_pos[(size_t)c * P + p]);
    g_S[b][n * P + p] = sigmoidf_(acc + g_beta[b][n]);
}

// ---------------- host ----------------
extern "C" void kernel_launch(void* const* d_in, const int* in_sizes, int n_in,
                              void* d_out, int out_size) {
    const float* x       = (const float*)d_in[0];
    const float* w_exp   = (const float*)d_in[1];
    const float* b_exp   = (const float*)d_in[2];
    const float* w_res   = (const float*)d_in[3];
    const float* b_res   = (const float*)d_in[4];
    const float* w_fus   = (const float*)d_in[5];
    const float* b_fus   = (const float*)d_in[6];
    const float* ch_wv_w = (const float*)d_in[7];
    const float* ch_wv_b = (const float*)d_in[8];
    const float* ch_wq_w = (const float*)d_in[9];
    const float* ch_wq_b = (const float*)d_in[10];
    const float* ch_wz_w = (const float*)d_in[11];
    const float* ch_wz_b = (const float*)d_in[12];
    const float* ln_g    = (const float*)d_in[13];
    const float* ln_b    = (const float*)d_in[14];
    const float* sp_wv_w = (const float*)d_in[15];
    const float* sp_wv_b = (const float*)d_in[16];
    const float* sp_wq_w = (const float*)d_in[17];
    const float* sp_wq_b = (const float*)d_in[18];

    float *p_expx, *p_bc;
    __nv_bfloat16 *p_WexpH, *p_WexpL, *p_WcatH, *p_WcatL;
    cudaGetSymbolAddress((void**)&p_expx, g_expx);
    cudaGetSymbolAddress((void**)&p_bc, g_bc);
    cudaGetSymbolAddress((void**)&p_WexpH, g_WexpH);
    cudaGetSymbolAddress((void**)&p_WexpL, g_WexpL);
    cudaGetSymbolAddress((void**)&p_WcatH, g_WcatH);
    cudaGetSymbolAddress((void**)&p_WcatL, g_WcatL);

    cudaFuncSetAttribute(gemm_mma3,
                         cudaFuncAttributeMaxDynamicSharedMemorySize, SM_BYTES);

    pos_kernel<<<(C * P) / 256, 256>>>();
    wcat_kernel<<<KFULL, 256>>>(w_fus, w_res);
    bc_kernel<<<1, 256>>>(w_fus, b_res, b_fus);
    wsplit_kernel<<<COUT3, 256>>>(w_exp, p_WexpH, p_WexpL, COUT3 * C);
    xprep_kernel<<<dim3(P / 32, C / 32, NB), 256>>>(x);

    // expx = W_exp @ x + b_exp
    gemm_mma3<<<dim3(P / 128, COUT3 / 128, NB), 256, SM_BYTES>>>(
        p_WexpH, p_WexpL, b_exp, p_expx, C, COUT3, 0);

    tq_kernel<<<dim3(P / 128, NB, 3), 128>>>(ch_wq_w, ch_wq_b);
    red_kernel<<<dim3(C, NB, 3), 256>>>();
    tiny_kernel<<<dim3(NB, 3), 256>>>(ch_wv_w, ch_wv_b, ch_wz_w, ch_wz_b,
                                      ln_g, ln_b, sp_wq_w, sp_wq_b,
                                      sp_wv_w, sp_wv_b);
    s_kernel<<<dim3(P / 128, NB, 3), 128>>>();

    // out = [Wc | W_fus] @ [gated-cat ; x] + bc
    gemm_mma3<<<dim3(P / 128, C / 128, NB), 256, SM_BYTES>>>(
        p_WcatH, p_WcatL, p_bc, (float*)d_out, KFULL, C, 1);
}

// round 7
// speedup vs baseline: 1.9429x; 1.0411x over previous
#include <cuda_runtime.h>
#include <cuda_bf16.h>
#include <math.h>
#include <stdint.h>

#define NB 8
#define C 256
#define C2 128
#define P 4096          // 64*64 pixels
#define COUT3 768
#define KFULL 1024      // 768 gated channels + 256 raw x channels

// ---------------- scratch (device globals; no allocs allowed) ----------------
__device__ float g_pos[C * P];                 // positional encoding, 4 MB
__device__ float g_expx[NB * COUT3 * P];       // X = expx + pos (stored fused)
__device__ float g_We[3][NB * P];              // w * exp(T) per pixel
__device__ float g_wcov[P];                    // coverage weights for win=6
__device__ float g_xs[3][NB * C];              // sum_p cnt*X
__device__ float g_ys[3][NB * C];              // sum_p cnt*e*X
__device__ float g_Z[3][NB];                   // sum_p cnt*e
__device__ float g_chw[3][NB * C];             // channel gate
__device__ float g_v[3][NB * C];               // spatial-gate projection vector
__device__ float g_beta[3][NB];                // spatial-gate bias
__device__ float g_S[3][NB * P];               // spatial gate per pixel
__device__ float g_bc[C];                      // W_fus @ b_res + b_fus

// pre-split operands (bf16 hi/lo)
__device__ __nv_bfloat16 g_WexpH[COUT3 * C], g_WexpL[COUT3 * C];
__device__ __nv_bfloat16 g_WcatH[C * KFULL], g_WcatL[C * KFULL];
__device__ __nv_bfloat16 g_xh[NB * P * C], g_xl[NB * P * C];   // [n][p][c]

// ================= helpers =================
__device__ __forceinline__ uint32_t smem_u32(const void* p) {
    uint32_t a;
    asm("{ .reg .u64 t; cvta.to.shared.u64 t, %1; cvt.u32.u64 %0, t; }"
        : "=r"(a) : "l"(p));
    return a;
}
__device__ __forceinline__ uint32_t swz(uint32_t b) { return b ^ ((b >> 3) & 0x70); }

__device__ __forceinline__ void split2(float a, float b, uint32_t& hp, uint32_t& lp) {
    __nv_bfloat16 ha = __float2bfloat16_rn(a);
    __nv_bfloat16 hb = __float2bfloat16_rn(b);
    __nv_bfloat16 la = __float2bfloat16_rn(a - __bfloat162float(ha));
    __nv_bfloat16 lb = __float2bfloat16_rn(b - __bfloat162float(hb));
    hp = (uint32_t)__bfloat16_as_ushort(ha) | ((uint32_t)__bfloat16_as_ushort(hb) << 16);
    lp = (uint32_t)__bfloat16_as_ushort(la) | ((uint32_t)__bfloat16_as_ushort(lb) << 16);
}

__device__ __forceinline__ void ldsm4(uint32_t a[4], uint32_t addr) {
    asm volatile("ldmatrix.sync.aligned.m8n8.x4.shared.b16 {%0,%1,%2,%3}, [%4];"
                 : "=r"(a[0]), "=r"(a[1]), "=r"(a[2]), "=r"(a[3]) : "r"(addr));
}
__device__ __forceinline__ void mma16816(float d[4], const uint32_t a[4],
                                         const uint32_t b0, const uint32_t b1) {
    asm volatile(
        "mma.sync.aligned.m16n8k16.row.col.f32.bf16.bf16.f32 "
        "{%0,%1,%2,%3}, {%4,%5,%6,%7}, {%8,%9}, {%0,%1,%2,%3};"
        : "+f"(d[0]), "+f"(d[1]), "+f"(d[2]), "+f"(d[3])
        : "r"(a[0]), "r"(a[1]), "r"(a[2]), "r"(a[3]), "r"(b0), "r"(b1));
}
__device__ __forceinline__ void cpasync16(uint32_t dst, const void* src) {
    asm volatile("cp.async.ca.shared.global [%0], [%1], 16;" :: "r"(dst), "l"(src));
}
__device__ __forceinline__ void cp_commit() {
    asm volatile("cp.async.commit_group;" ::: "memory");
}
__device__ __forceinline__ void cp_wait2() {
    asm volatile("cp.async.wait_group 2;" ::: "memory");
}

// ======= pipelined mma.sync GEMM: Y[n,o,p] = sum_c A[o,c] B[c,p] + bias =======
// CTA 256 thr, tile M=128 x N=128, K-chunk 32, 3-stage cp.async pipeline.
// Stage layout: A tile 128 rows x 128B (hi k0..31 in bytes [0,64), lo in [64,128)),
// B tile same. Stage = 32 KB; 3 stages = 96 KB -> 2 CTAs/SM.
#define STG 32768
#define SM_BYTES (3 * STG)

__global__ void __launch_bounds__(256, 2)
gemm_mma4(const __nv_bfloat16* __restrict__ WH, const __nv_bfloat16* __restrict__ WL,
          const float* __restrict__ bias, float* __restrict__ Y,
          int Cin, int Cout, int mode, const float* __restrict__ pos_add)
{
    extern __shared__ char smem[];
    uint32_t sb = smem_u32(smem);
    int tid = threadIdx.x, wid = tid >> 5, lane = tid & 31;
    int n = blockIdx.z;
    int row0 = blockIdx.y * 128, col0 = blockIdx.x * 128;
    float* Yn = Y + (size_t)n * Cout * P;

    int warp_m = wid >> 2;   // 0..1 -> 64 rows
    int warp_n = wid & 3;    // 0..3 -> 32 cols

    float acc[4][4][4];
#pragma unroll
    for (int i = 0; i < 4; i++)
#pragma unroll
        for (int j = 0; j < 4; j++)
#pragma unroll
            for (int k = 0; k < 4; k++) acc[i][j][k] = 0.f;

    int l7 = lane & 7;
    int aRowOff = ((lane >> 3) & 1) * 8 + l7;
    int aKOff16 = (lane >> 4) * 16;
    int bRowOff = ((lane >> 4) & 1) * 8 + l7;
    int bColOff = ((lane >> 3) & 1) * 16;

    int nchunks = Cin >> 5;

    auto load_stage = [&](int ch, int s) {
        int c0 = ch << 5;
        uint32_t stA = sb + s * STG;
        uint32_t stB = stA + 16384;
        // A: 128 rows x (hi 64B + lo 64B) = 1024 x 16B / 256 thr = 4 each
#pragma unroll
        for (int i = 0; i < 4; i++) {
            int idx = i * 256 + tid;
            int row = idx >> 3, slot = idx & 7;
            int til = slot >> 2, q = slot & 3;
            const __nv_bfloat16* src =
                (til ? WL : WH) + (size_t)(row0 + row) * Cin + c0 + q * 8;
            uint32_t dst = stA + swz((uint32_t)(row * 128 + til * 64 + q * 16));
            cpasync16(dst, src);
        }
        bool gated = (mode == 1) && (c0 < COUT3);
        if (!gated) {
            int xc0 = (mode == 1) ? c0 - COUT3 : c0;
#pragma unroll
            for (int i = 0; i < 4; i++) {
                int idx = i * 256 + tid;
                int row = idx >> 3, slot = idx & 7;
                int til = slot >> 2, q = slot & 3;
                const __nv_bfloat16* src =
                    (til ? g_xl : g_xh) + ((size_t)n * P + col0 + row) * C + xc0 + q * 8;
                uint32_t dst = stB + swz((uint32_t)(row * 128 + til * 64 + q * 16));
                cpasync16(dst, src);
            }
        } else {
            char* smB = smem + s * STG + 16384;
            int row = tid & 127, half = tid >> 7;  // half: k 0..15 / 16..31
            int pg = col0 + row;
            int b = c0 >> 8;
            float Sp1 = 1.f + g_S[b][n * P + pg];
#pragma unroll
            for (int cq = 0; cq < 16; cq += 4) {
                int kk = half * 16 + cq;
                int cglob = c0 + kk;
                int cl = (c0 & 255) + kk;
                const float* Xc = &g_expx[((size_t)n * COUT3 + cglob) * P + pg];
                const float* pc = &g_pos[(size_t)cl * P + pg];
                const float* cw = &g_chw[b][n * C + cl];
                float val[4];
#pragma unroll
                for (int j = 0; j < 4; j++) {
                    float Xv = Xc[(size_t)j * P];
                    val[j] = Xv * (Sp1 + cw[j]) - pc[(size_t)j * P];
                }
                uint32_t h0, l0, h1, l1;
                split2(val[0], val[1], h0, l0);
                split2(val[2], val[3], h1, l1);
                uint32_t offH = swz((uint32_t)(row * 128 + kk * 2));
                uint32_t offL = swz((uint32_t)(row * 128 + 64 + kk * 2));
                *(uint2*)(smB + offH) = make_uint2(h0, h1);
                *(uint2*)(smB + offL) = make_uint2(l0, l1);
            }
        }
    };

    // prologue: stages 0..2
#pragma unroll
    for (int s = 0; s < 3; s++) {
        load_stage(s, s);
        cp_commit();
    }

    int s = 0;
    for (int ch = 0; ch < nchunks; ch++) {
        cp_wait2();
        __syncthreads();
        uint32_t stA = sb + s * STG;
        uint32_t stB = stA + 16384;
#pragma unroll
        for (int ks = 0; ks < 2; ks++) {
            int kb = ks * 32;
            uint32_t aH[4][4], aL[4][4];
#pragma unroll
            for (int mi = 0; mi < 4; mi++) {
                int row = warp_m * 64 + mi * 16 + aRowOff;
                ldsm4(aH[mi], stA + swz((uint32_t)(row * 128 + kb + aKOff16)));
                ldsm4(aL[mi], stA + swz((uint32_t)(row * 128 + 64 + kb + aKOff16)));
            }
#pragma unroll
            for (int nip = 0; nip < 2; nip++) {
                int row = warp_n * 32 + nip * 16 + bRowOff;
                uint32_t offH = swz((uint32_t)(row * 128 + kb + bColOff));
                uint32_t offL = swz((uint32_t)(row * 128 + 64 + kb + bColOff));
                uint32_t bH[4], bL[4];
                ldsm4(bH, stB + offH);
                ldsm4(bL, stB + offL);
#pragma unroll
                for (int mi = 0; mi < 4; mi++) {
                    mma16816(acc[mi][2 * nip], aH[mi], bH[0], bH[1]);
                    mma16816(acc[mi][2 * nip], aH[mi], bL[0], bL[1]);
                    mma16816(acc[mi][2 * nip], aL[mi], bH[0], bH[1]);
                    mma16816(acc[mi][2 * nip + 1], aH[mi], bH[2], bH[3]);
                    mma16816(acc[mi][2 * nip + 1], aH[mi], bL[2], bL[3]);
                    mma16816(acc[mi][2 * nip + 1], aL[mi], bH[2], bH[3]);
                }
            }
        }
        __syncthreads();
        if (ch + 3 < nchunks) load_stage(ch + 3, s);
        cp_commit();   // always commit (empty group keeps wait_group math exact)
        s++;
        if (s == 3) s = 0;
    }

    // ---- epilogue ----
    int r = lane >> 2, q = lane & 3;
#pragma unroll
    for (int mi = 0; mi < 4; mi++) {
        int o = row0 + warp_m * 64 + mi * 16 + r;
        float b0 = bias[o];
        float b8 = bias[o + 8];
#pragma unroll
        for (int ni = 0; ni < 4; ni++) {
            int p = col0 + warp_n * 32 + ni * 8 + q * 2;
            size_t i0 = (size_t)o * P + p;
            size_t i1 = (size_t)(o + 8) * P + p;
            float2 v0 = make_float2(acc[mi][ni][0] + b0, acc[mi][ni][1] + b0);
            float2 v1 = make_float2(acc[mi][ni][2] + b8, acc[mi][ni][3] + b8);
            if (pos_add) {
                size_t q0 = (size_t)(o & 255) * P + p;
                size_t q1 = (size_t)((o + 8) & 255) * P + p;
                float2 p0 = *(const float2*)&pos_add[q0];
                float2 p1 = *(const float2*)&pos_add[q1];
                v0.x += p0.x; v0.y += p0.y;
                v1.x += p1.x; v1.y += p1.y;
            }
            *(float2*)&Yn[i0] = v0;
            *(float2*)&Yn[i1] = v1;
        }
    }
}

// =========================== prep kernels ===========================
__global__ void wsplit_kernel(const float* __restrict__ W,
                              __nv_bfloat16* __restrict__ H,
                              __nv_bfloat16* __restrict__ L, int total) {
    int idx = blockIdx.x * 256 + threadIdx.x;
    if (idx < total) {
        float v = W[idx];
        __nv_bfloat16 h = __float2bfloat16_rn(v);
        H[idx] = h;
        L[idx] = __float2bfloat16_rn(v - __bfloat162float(h));
    }
}

// transpose + split x: [n][c][p] -> xh/xl [n][p][c]
__global__ __launch_bounds__(256) void xprep_kernel(const float* __restrict__ x) {
    __shared__ float tile[32][33];
    int n = blockIdx.z;
    int p0 = blockIdx.x * 32, c0 = blockIdx.y * 32;
    int tx = threadIdx.x & 31, ty = threadIdx.x >> 5;  // 32x8
    for (int i = ty; i < 32; i += 8)
        tile[i][tx] = x[((size_t)n * C + c0 + i) * P + p0 + tx];
    __syncthreads();
    for (int i = ty; i < 32; i += 8) {
        float v = tile[tx][i];   // (c = c0+tx, p = p0+i)
        __nv_bfloat16 h = __float2bfloat16_rn(v);
        size_t dst = ((size_t)n * P + p0 + i) * C + c0 + tx;
        g_xh[dst] = h;
        g_xl[dst] = __float2bfloat16_rn(v - __bfloat162float(h));
    }
}

// g_WcatH/L = split([W_fus @ W_res | W_fus])
__global__ __launch_bounds__(256) void wcat_kernel(const float* __restrict__ Wf,
                                                   const float* __restrict__ Wr) {
    int c = blockIdx.x;  // < 1024
    int o = threadIdx.x;
    float a;
    if (c < COUT3) {
        __shared__ float col[C];
        col[o] = Wr[o * COUT3 + c];
        __syncthreads();
        const float* row = Wf + o * C;
        a = 0.f;
#pragma unroll 8
        for (int m = 0; m < C; m++) a += row[m] * col[m];
    } else {
        a = Wf[o * C + (c - COUT3)];
    }
    __nv_bfloat16 h = __float2bfloat16_rn(a);
    g_WcatH[o * KFULL + c] = h;
    g_WcatL[o * KFULL + c] = __float2bfloat16_rn(a - __bfloat162float(h));
}

__global__ __launch_bounds__(256) void bc_kernel(const float* __restrict__ Wf,
                                                 const float* __restrict__ br,
                                                 const float* __restrict__ bf) {
    int o = threadIdx.x;
    float a = 0.f;
#pragma unroll 8
    for (int m = 0; m < C; m++) a += Wf[o * C + m] * br[m];
    g_bc[o] = a + bf[o];
}

// =========================== non-GEMM kernels ===========================
__device__ __forceinline__ int cov6(int h) {
    int r = 0;
#pragma unroll
    for (int j = 0; j < 6; j++) r += (h >= 10 * j) && (h <= 10 * j + 13);
    return r;
}
__device__ __forceinline__ float sigmoidf_(float x) { return 1.0f / (1.0f + expf(-x)); }

__global__ void pos_kernel() {
    int idx = blockIdx.x * blockDim.x + threadIdx.x;  // < C*P
    int prow = idx >> 8;
    int c = idx & 255;
    int i = prow >> 6;
    int j = prow & 63;
    int k = c & 63;
    float omega = powf(10000.0f, -(float)k / 64.0f);
    float coord = (c < 128) ? (float)i : (float)j;
    float a = coord * omega;
    float val = ((c >> 6) & 1) ? cosf(a) : sinf(a);
    g_pos[idx] = val;
    if (idx < P) {
        int h = idx >> 6, w = idx & 63;
        g_wcov[idx] = (float)(cov6(h) * cov6(w));
    }
}

__global__ __launch_bounds__(128) void tq_kernel(const float* __restrict__ wq,
                                                 const float* __restrict__ bq) {
    int b = blockIdx.z, n = blockIdx.y;
    int p = blockIdx.x * 128 + threadIdx.x;
    __shared__ float wqs[C];
    for (int c = threadIdx.x; c < C; c += 128) wqs[c] = wq[c];
    __syncthreads();
    const float* Xb = g_expx + ((size_t)n * COUT3 + b * C) * P;
    float acc = 0.f;
#pragma unroll 8
    for (int c = 0; c < C; c++) acc += wqs[c] * Xb[(size_t)c * P + p];
    float T = acc + bq[0];
    float w = (b == 2) ? g_wcov[p] : 1.f;
    g_We[b][n * P + p] = w * expf(T);
}

__global__ __launch_bounds__(256) void red_kernel() {
    int b = blockIdx.z, n = blockIdx.y, c = blockIdx.x;
    const float* Xc = g_expx + ((size_t)n * COUT3 + b * C + c) * P;
    const float* Wn = &g_We[b][n * P];
    float xs = 0.f, ys = 0.f, zs = 0.f;
    for (int t = threadIdx.x; t < P; t += 256) {
        float w = (b == 2) ? g_wcov[t] : 1.f;
        float X = Xc[t];
        float we = Wn[t];
        xs += w * X;
        ys += we * X;
        zs += we;
    }
    __shared__ float red[256];
    int t = threadIdx.x;
    red[t] = xs; __syncthreads();
    for (int s = 128; s > 0; s >>= 1) { if (t < s) red[t] += red[t + s]; __syncthreads(); }
    if (t == 0) g_xs[b][n * C + c] = red[0];
    __syncthreads();
    red[t] = ys; __syncthreads();
    for (int s = 128; s > 0; s >>= 1) { if (t < s) red[t] += red[t + s]; __syncthreads(); }
    if (t == 0) g_ys[b][n * C + c] = red[0];
    __syncthreads();
    red[t] = zs; __syncthreads();
    for (int s = 128; s > 0; s >>= 1) { if (t < s) red[t] += red[t + s]; __syncthreads(); }
    if (t == 0 && c == 0) g_Z[b][n] = red[0];
}

__global__ __launch_bounds__(256) void tiny_kernel(
    const float* __restrict__ Wv, const float* __restrict__ bv,
    const float* __restrict__ Wz, const float* __restrict__ bz,
    const float* __restrict__ lg, const float* __restrict__ lb,
    const float* __restrict__ Wqs, const float* __restrict__ bqs,
    const float* __restrict__ Wvs, const float* __restrict__ bvs)
{
    int n = blockIdx.x, b = blockIdx.y;
    __shared__ float y[C], xb[C], zz[C2], sq[C2], wzs[C], red[256];
    int t = threadIdx.x;
    float L = (b == 2) ? 7056.f : 4096.f;
    float Zn = g_Z[b][n];
    y[t] = g_ys[b][n * C + t] / Zn;
    xb[t] = g_xs[b][n * C + t] / L;
    __syncthreads();

    if (t < C2) {
        float a = 0.f;
        for (int c = 0; c < C; c++) a += Wv[t * C + c] * y[c];
        zz[t] = a + bv[t];
    }
    __syncthreads();

    {
        float a = 0.f;
        for (int c2 = 0; c2 < C2; c2++) a += Wz[t * C2 + c2] * zz[c2];
        wzs[t] = a + bz[t];
    }
    __syncthreads();

    red[t] = wzs[t]; __syncthreads();
    for (int s = 128; s > 0; s >>= 1) { if (t < s) red[t] += red[t + s]; __syncthreads(); }
    float m = red[0] / 256.f; __syncthreads();
    float d = wzs[t] - m;
    red[t] = d * d; __syncthreads();
    for (int s = 128; s > 0; s >>= 1) { if (t < s) red[t] += red[t + s]; __syncthreads(); }
    float var = red[0] / 256.f; __syncthreads();
    g_chw[b][n * C + t] = sigmoidf_(d * rsqrtf(var + 1e-5f) * lg[t] + lb[t]);

    if (t < C2) {
        float a = 0.f;
        for (int c = 0; c < C; c++) a += Wqs[t * C + c] * xb[c];
        zz[t] = a + bqs[t];
    }
    __syncthreads();
    red[t] = (t < C2) ? zz[t] : -1e30f; __syncthreads();
    for (int s = 128; s > 0; s >>= 1) { if (t < s) red[t] = fmaxf(red[t], red[t + s]); __syncthreads(); }
    float mx = red[0]; __syncthreads();
    float e = (t < C2) ? expf(zz[t] - mx) : 0.f;
    if (t < C2) sq[t] = e;
    red[t] = e; __syncthreads();
    for (int s = 128; s > 0; s >>= 1) { if (t < s) red[t] += red[t + s]; __syncthreads(); }
    float se = red[0]; __syncthreads();
    if (t < C2) sq[t] /= se;
    __syncthreads();

    {
        float a = 0.f;
        for (int c2 = 0; c2 < C2; c2++) a += sq[c2] * Wvs[c2 * C + t];
        g_v[b][n * C + t] = a;
    }
    red[t] = (t < C2) ? sq[t] * bvs[t] : 0.f; __syncthreads();
    for (int s = 128; s > 0; s >>= 1) { if (t < s) red[t] += red[t + s]; __syncthreads(); }
    if (t == 0) g_beta[b][n] = red[0];
}

__global__ __launch_bounds__(128) void s_kernel() {
    int b = blockIdx.z, n = blockIdx.y;
    int p = blockIdx.x * 128 + threadIdx.x;
    __shared__ float vs[C];
    for (int c = threadIdx.x; c < C; c += 128) vs[c] = g_v[b][n * C + c];
    __syncthreads();
    const float* Xb = g_expx + ((size_t)n * COUT3 + b * C) * P;
    float acc = 0.f;
#pragma unroll 8
    for (int c = 0; c < C; c++) acc += vs[c] * Xb[(size_t)c * P + p];
    g_S[b][n * P + p] = sigmoidf_(acc + g_beta[b][n]);
}

// ---------------- host ----------------
extern "C" void kernel_launch(void* const* d_in, const int* in_sizes, int n_in,
                              void* d_out, int out_size) {
    const float* x       = (const float*)d_in[0];
    const float* w_exp   = (const float*)d_in[1];
    const float* b_exp   = (const float*)d_in[2];
    const float* w_res   = (const float*)d_in[3];
    const float* b_res   = (const float*)d_in[4];
    const float* w_fus   = (const float*)d_in[5];
    const float* b_fus   = (const float*)d_in[6];
    const float* ch_wv_w = (const float*)d_in[7];
    const float* ch_wv_b = (const float*)d_in[8];
    const float* ch_wq_w = (const float*)d_in[9];
    const float* ch_wq_b = (const float*)d_in[10];
    const float* ch_wz_w = (const float*)d_in[11];
    const float* ch_wz_b = (const float*)d_in[12];
    const float* ln_g    = (const float*)d_in[13];
    const float* ln_b    = (const float*)d_in[14];
    const float* sp_wv_w = (const float*)d_in[15];
    const float* sp_wv_b = (const float*)d_in[16];
    const float* sp_wq_w = (const float*)d_in[17];
    const float* sp_wq_b = (const float*)d_in[18];

    float *p_expx, *p_bc, *p_pos;
    __nv_bfloat16 *p_WexpH, *p_WexpL, *p_WcatH, *p_WcatL;
    cudaGetSymbolAddress((void**)&p_expx, g_expx);
    cudaGetSymbolAddress((void**)&p_bc, g_bc);
    cudaGetSymbolAddress((void**)&p_pos, g_pos);
    cudaGetSymbolAddress((void**)&p_WexpH, g_WexpH);
    cudaGetSymbolAddress((void**)&p_WexpL, g_WexpL);
    cudaGetSymbolAddress((void**)&p_WcatH, g_WcatH);
    cudaGetSymbolAddress((void**)&p_WcatL, g_WcatL);

    cudaFuncSetAttribute(gemm_mma4,
                         cudaFuncAttributeMaxDynamicSharedMemorySize, SM_BYTES);

    pos_kernel<<<(C * P) / 256, 256>>>();
    wcat_kernel<<<KFULL, 256>>>(w_fus, w_res);
    bc_kernel<<<1, 256>>>(w_fus, b_res, b_fus);
    wsplit_kernel<<<COUT3, 256>>>(w_exp, p_WexpH, p_WexpL, COUT3 * C);
    xprep_kernel<<<dim3(P / 32, C / 32, NB), 256>>>(x);

    // g_expx = X = W_exp @ x + b_exp + pos  (pos fused in epilogue)
    gemm_mma4<<<dim3(P / 128, COUT3 / 128, NB), 256, SM_BYTES>>>(
        p_WexpH, p_WexpL, b_exp, p_expx, C, COUT3, 0, p_pos);

    tq_kernel<<<dim3(P / 128, NB, 3), 128>>>(ch_wq_w, ch_wq_b);
    red_kernel<<<dim3(C, NB, 3), 256>>>();
    tiny_kernel<<<dim3(NB, 3), 256>>>(ch_wv_w, ch_wv_b, ch_wz_w, ch_wz_b,
                                      ln_g, ln_b, sp_wq_w, sp_wq_b,
                                      sp_wv_w, sp_wv_b);
    s_kernel<<<dim3(P / 128, NB, 3), 128>>>();

    // out = [Wc | W_fus] @ [gated-cat ; x] + bc   (gating fused into B-loader)
    gemm_mma4<<<dim3(P / 128, C / 128, NB), 256, SM_BYTES>>>(
        p_WcatH, p_WcatL, p_bc, (float*)d_out, KFULL, C, 1, nullptr);
}